// round 1
// baseline (speedup 1.0000x reference)
#include <cuda_runtime.h>
#include <math.h>

// Problem constants
#define NN   16384
#define DD   512
#define BSZ  16
#define MM   256
#define HHD  8
#define LL   4

// ---------------- scratch (device globals; no allocs allowed) ----------------
__device__ float g_h [NN*DD];
__device__ float g_ln[NN*DD];
__device__ float g_q [NN*DD];
__device__ float g_xw[NN*DD];
__device__ float g_ao[NN*DD];
__device__ float g_k [BSZ*MM*DD];
__device__ float g_v [BSZ*MM*DD];
__device__ float g_u [(size_t)NN*4096];
__device__ float g_f [(size_t)NN*2048];
__device__ float g_mu[DD];
__device__ float g_var[DD];
__device__ float g_scale[DD];
__device__ float g_shift[DD];
__device__ float g_deg [NN];
__device__ float g_dinv[NN];
__device__ int   g_is64;

// ---------------- helpers ----------------
__device__ __forceinline__ int edge_at(const void* ei, long long pos) {
    if (g_is64) return (int)((const long long*)ei)[pos];
    return ((const int*)ei)[pos];
}

__device__ __forceinline__ float gelu_exact(float x) {
    return 0.5f * x * (1.0f + erff(x * 0.70710678118654752f));
}

// ---------------- init: deg=1 (self loop), zero bn stats ----------------
__global__ void init_kernel() {
    int i = blockIdx.x * blockDim.x + threadIdx.x;
    if (i < NN) g_deg[i] = 1.0f;
    if (i < DD) { g_mu[i] = 0.0f; g_var[i] = 0.0f; }
}

// ---------------- edge-index dtype sniffer ----------------
// If data is int64 (values < 2^31, nonneg), every high 32-bit word is 0.
// If data is int32, the "high words" are actual random indices -> mostly nonzero.
__global__ void detect_kernel(const unsigned int* __restrict__ raw, int n) {
    __shared__ int any;
    if (threadIdx.x == 0) any = 0;
    __syncthreads();
    int local = 0;
    for (int j = threadIdx.x; j < n; j += blockDim.x)
        if (raw[2*j + 1] != 0u) local = 1;
    if (local) atomicOr(&any, 1);
    __syncthreads();
    if (threadIdx.x == 0) g_is64 = any ? 0 : 1;
}

// ---------------- BatchNorm (training-mode batch stats) ----------------
__global__ void bn_stats_kernel(const float* __restrict__ x) {
    int c = threadIdx.x;                       // 512 threads = 512 cols
    size_t r0 = (size_t)blockIdx.x * 128;      // 128 blocks x 128 rows
    float s = 0.f, sq = 0.f;
    for (int r = 0; r < 128; r++) {
        float v = x[(r0 + r) * DD + c];
        s += v; sq += v * v;
    }
    atomicAdd(&g_mu[c], s);
    atomicAdd(&g_var[c], sq);
}

__global__ void bn_final_kernel(const float* __restrict__ w, const float* __restrict__ b) {
    int c = threadIdx.x;  // 512
    float mu  = g_mu[c]  * (1.0f / NN);
    float var = g_var[c] * (1.0f / NN) - mu * mu;
    float sc  = w[c] * rsqrtf(var + 1e-5f);
    g_scale[c] = sc;
    g_shift[c] = b[c] - mu * sc;
}

__global__ void bn_apply_kernel(const float* __restrict__ x) {
    size_t idx = (size_t)blockIdx.x * blockDim.x + threadIdx.x;  // float4 index, N*128
    int c4 = (int)(idx & 127);
    float4 xv = ((const float4*)x)[idx];
    float4 sc = ((const float4*)g_scale)[c4];
    float4 sh = ((const float4*)g_shift)[c4];
    float4 r;
    r.x = xv.x * sc.x + sh.x; r.y = xv.y * sc.y + sh.y;
    r.z = xv.z * sc.z + sh.z; r.w = xv.w * sc.w + sh.w;
    ((float4*)g_ln)[idx] = r;
}

// ---------------- GCN degree / dinv ----------------
__global__ void deg_kernel(const void* __restrict__ ei, long long E) {
    long long stride = (long long)gridDim.x * blockDim.x;
    for (long long e = (long long)blockIdx.x * blockDim.x + threadIdx.x; e < E; e += stride) {
        int d = edge_at(ei, E + e);
        atomicAdd(&g_deg[d], 1.0f);
    }
}

__global__ void dinv_kernel() {
    int i = blockIdx.x * blockDim.x + threadIdx.x;
    if (i < NN) g_dinv[i] = rsqrtf(g_deg[i]);
}

// init gcn output: bias + self-loop term (+ optional input residual)
template<bool ADDX>
__global__ void gcn_init_kernel(const float* __restrict__ bias,
                                const float* __restrict__ xin,
                                float* __restrict__ dst) {
    size_t idx = (size_t)blockIdx.x * blockDim.x + threadIdx.x;  // float4, N*128
    size_t row = idx >> 7;
    int c4 = (int)(idx & 127);
    float d2 = g_dinv[row]; d2 *= d2;
    float4 xw = ((const float4*)g_xw)[idx];
    float4 bb = ((const float4*)bias)[c4];
    float4 r;
    r.x = bb.x + d2 * xw.x; r.y = bb.y + d2 * xw.y;
    r.z = bb.z + d2 * xw.z; r.w = bb.w + d2 * xw.w;
    if (ADDX) {
        float4 xv = ((const float4*)xin)[idx];
        r.x += xv.x; r.y += xv.y; r.z += xv.z; r.w += xv.w;
    }
    ((float4*)dst)[idx] = r;
}

// one block per edge; 128 threads x float4
__global__ void gcn_scatter_kernel(const void* __restrict__ ei, long long E,
                                   const float* __restrict__ xw, float* __restrict__ dst) {
    long long e = blockIdx.x;
    int s = edge_at(ei, e);
    int d = edge_at(ei, E + e);
    float norm = g_dinv[s] * g_dinv[d];
    const float4* sp = (const float4*)(xw + (size_t)s * DD);
    float* dp = dst + (size_t)d * DD;
    int c = threadIdx.x;  // 128 threads, one float4 each
    float4 v = sp[c];
    atomicAdd(&dp[c*4 + 0], v.x * norm);
    atomicAdd(&dp[c*4 + 1], v.y * norm);
    atomicAdd(&dp[c*4 + 2], v.z * norm);
    atomicAdd(&dp[c*4 + 3], v.w * norm);
}

// ---------------- LayerNorm (row-wise over 512) ----------------
__global__ void ln_kernel(const float* __restrict__ x, const float* __restrict__ w,
                          const float* __restrict__ b, float* __restrict__ y) {
    __shared__ float red[8];
    size_t row = blockIdx.x;
    int t = threadIdx.x;  // 128 threads, float4 each
    float4 v = ((const float4*)(x + row * DD))[t];
    float s  = v.x + v.y + v.z + v.w;
    float sq = v.x*v.x + v.y*v.y + v.z*v.z + v.w*v.w;
    for (int o = 16; o; o >>= 1) {
        s  += __shfl_xor_sync(0xffffffffu, s,  o);
        sq += __shfl_xor_sync(0xffffffffu, sq, o);
    }
    if ((t & 31) == 0) { red[t >> 5] = s; red[4 + (t >> 5)] = sq; }
    __syncthreads();
    s  = red[0] + red[1] + red[2] + red[3];
    sq = red[4] + red[5] + red[6] + red[7];
    float mean = s * (1.0f / DD);
    float var  = sq * (1.0f / DD) - mean * mean;
    float rstd = rsqrtf(var + 1e-5f);
    float4 wv = ((const float4*)w)[t];
    float4 bv = ((const float4*)b)[t];
    float4 o4;
    o4.x = (v.x - mean) * rstd * wv.x + bv.x;
    o4.y = (v.y - mean) * rstd * wv.y + bv.y;
    o4.z = (v.z - mean) * rstd * wv.z + bv.z;
    o4.w = (v.w - mean) * rstd * wv.w + bv.w;
    ((float4*)(y + row * DD))[t] = o4;
}

// ---------------- SGEMM: C[M,N] (+)= A[M,K] @ B[K,N] (+ bias) ----------------
// 128x64x16 tiles, 256 threads, 8x4 micro-tile per thread.
template<bool ACCUM, bool BIAS>
__global__ void __launch_bounds__(256, 2) gemm_kernel(
    const float* __restrict__ A, const float* __restrict__ B,
    const float* __restrict__ bias, float* __restrict__ C,
    int Mdim, int Ndim, int Kdim)
{
    __shared__ float  As[16][128];
    __shared__ float4 Bs[16][16];
    int tid = threadIdx.x;
    int tx = tid & 15, ty = tid >> 4;
    int row0 = blockIdx.y * 128;
    int col0 = blockIdx.x * 64;
    float acc[8][4];
#pragma unroll
    for (int r = 0; r < 8; r++)
#pragma unroll
        for (int c = 0; c < 4; c++) acc[r][c] = 0.f;

    int ar  = tid >> 1;           // A tile row 0..127
    int ac0 = (tid & 1) * 2;      // first of two float4 cols
    const float* Abase = A + (size_t)(row0 + ar) * Kdim;
    int bk = tid >> 4, bn = tid & 15;
    const float* Bbase = B + (size_t)bk * Ndim + col0 + bn * 4;

    for (int k0 = 0; k0 < Kdim; k0 += 16) {
#pragma unroll
        for (int s = 0; s < 2; s++) {
            float4 a = *(const float4*)(Abase + k0 + (ac0 + s) * 4);
            As[(ac0 + s)*4 + 0][ar] = a.x;
            As[(ac0 + s)*4 + 1][ar] = a.y;
            As[(ac0 + s)*4 + 2][ar] = a.z;
            As[(ac0 + s)*4 + 3][ar] = a.w;
        }
        Bs[bk][bn] = *(const float4*)(Bbase + (size_t)k0 * Ndim);
        __syncthreads();
#pragma unroll
        for (int kk = 0; kk < 16; kk++) {
            float4 b4 = Bs[kk][tx];
            float4 a0 = *(const float4*)&As[kk][ty*8];
            float4 a1 = *(const float4*)&As[kk][ty*8 + 4];
            float a[8] = {a0.x, a0.y, a0.z, a0.w, a1.x, a1.y, a1.z, a1.w};
#pragma unroll
            for (int r = 0; r < 8; r++) {
                acc[r][0] += a[r] * b4.x;
                acc[r][1] += a[r] * b4.y;
                acc[r][2] += a[r] * b4.z;
                acc[r][3] += a[r] * b4.w;
            }
        }
        __syncthreads();
    }
    float4 bv = make_float4(0.f, 0.f, 0.f, 0.f);
    if (BIAS) bv = *(const float4*)(bias + col0 + tx * 4);
#pragma unroll
    for (int r = 0; r < 8; r++) {
        size_t off = (size_t)(row0 + ty*8 + r) * Ndim + col0 + tx * 4;
        float4 v;
        v.x = acc[r][0]; v.y = acc[r][1]; v.z = acc[r][2]; v.w = acc[r][3];
        if (BIAS) { v.x += bv.x; v.y += bv.y; v.z += bv.z; v.w += bv.w; }
        if (ACCUM) {
            float4 o = *(const float4*)(C + off);
            v.x += o.x; v.y += o.y; v.z += o.z; v.w += o.w;
        }
        *(float4*)(C + off) = v;
    }
}

// ---------------- fused attention ----------------
// grid = BS * H * 8 chunks; block 256 threads; K/V resident in smem (stride-65 pad).
#define ATTN_SMEM ((2*256*65 + 8*256 + 8*64) * 4)

__global__ void attn_kernel(const float* __restrict__ q, const float* __restrict__ k,
                            const float* __restrict__ v, float* __restrict__ o)
{
    extern __shared__ float sm[];
    float* Ks = sm;
    float* Vs = sm + 256*65;
    float* Ps = Vs + 256*65;
    float* Qs = Ps + 8*256;
    int chunk = blockIdx.x & 7;
    int hh    = (blockIdx.x >> 3) & 7;
    int b     = blockIdx.x >> 6;
    int tid = threadIdx.x;
    int w = tid >> 5, l = tid & 31;

    for (int j = tid; j < 256*16; j += 256) {
        int m = j >> 4, f = j & 15;
        size_t g = (size_t)(b*256 + m) * DD + hh*64 + f*4;
        float4 kv = *(const float4*)(k + g);
        float4 vv = *(const float4*)(v + g);
        float* kd = &Ks[m*65 + f*4];
        kd[0] = kv.x; kd[1] = kv.y; kd[2] = kv.z; kd[3] = kv.w;
        float* vd = &Vs[m*65 + f*4];
        vd[0] = vv.x; vd[1] = vv.y; vd[2] = vv.z; vd[3] = vv.w;
    }
    __syncthreads();

    float* myP = Ps + w*256;
    float* myQ = Qs + w*64;
    for (int qi = w; qi < 128; qi += 8) {
        size_t gr   = (size_t)b*1024 + chunk*128 + qi;
        size_t qoff = gr * DD + hh*64;
        myQ[l]      = q[qoff + l]      * 0.125f;   // fold 1/sqrt(DH)
        myQ[l + 32] = q[qoff + l + 32] * 0.125f;
        __syncwarp();
        float s[8];
#pragma unroll
        for (int t = 0; t < 8; t++) s[t] = 0.f;
        for (int d = 0; d < 64; d++) {
            float qd = myQ[d];
#pragma unroll
            for (int t = 0; t < 8; t++) s[t] += qd * Ks[(l + 32*t)*65 + d];
        }
        float mx = s[0];
#pragma unroll
        for (int t = 1; t < 8; t++) mx = fmaxf(mx, s[t]);
        for (int off = 16; off; off >>= 1) mx = fmaxf(mx, __shfl_xor_sync(0xffffffffu, mx, off));
        float sum = 0.f;
#pragma unroll
        for (int t = 0; t < 8; t++) { s[t] = __expf(s[t] - mx); sum += s[t]; }
        for (int off = 16; off; off >>= 1) sum += __shfl_xor_sync(0xffffffffu, sum, off);
        float inv = 1.0f / sum;
#pragma unroll
        for (int t = 0; t < 8; t++) myP[l + 32*t] = s[t] * inv;
        __syncwarp();
        float o0 = 0.f, o1 = 0.f;
#pragma unroll 4
        for (int j = 0; j < 256; j++) {
            float p = myP[j];
            o0 += p * Vs[j*65 + l];
            o1 += p * Vs[j*65 + l + 32];
        }
        o[qoff + l]      = o0;
        o[qoff + l + 32] = o1;
        __syncwarp();
    }
}

// ---------------- GEGLU elementwise ----------------
__global__ void geglu_kernel() {
    size_t idx = (size_t)blockIdx.x * blockDim.x + threadIdx.x;  // float4 idx, N*512
    size_t row = idx >> 9;
    int c4 = (int)(idx & 511);
    float4 val = ((const float4*)g_u)[row*1024 + c4];
    float4 gt  = ((const float4*)g_u)[row*1024 + 512 + c4];
    float4 r;
    r.x = val.x * gelu_exact(gt.x);
    r.y = val.y * gelu_exact(gt.y);
    r.z = val.z * gelu_exact(gt.z);
    r.w = val.w * gelu_exact(gt.w);
    ((float4*)g_f)[idx] = r;
}

// ---------------- launch ----------------
extern "C" void kernel_launch(void* const* d_in, const int* in_sizes, int n_in,
                              void* d_out, int out_size)
{
    const float* x         = (const float*)d_in[0];
    const void*  ei        = d_in[1];
    const float* cond      = (const float*)d_in[2];
    const float* bn_w      = (const float*)d_in[3];
    const float* bn_b      = (const float*)d_in[4];
    const float* gcn_in_w  = (const float*)d_in[5];
    const float* gcn_in_b  = (const float*)d_in[6];
    const float* gcn_out_w = (const float*)d_in[7];
    const float* gcn_out_b = (const float*)d_in[8];
    const float* Wq        = (const float*)d_in[9];
    const float* Wk        = (const float*)d_in[10];
    const float* Wv        = (const float*)d_in[11];
    const float* Wo        = (const float*)d_in[12];
    const float* ln2_w     = (const float*)d_in[13];
    const float* ln2_b     = (const float*)d_in[14];
    const float* ln3_w     = (const float*)d_in[15];
    const float* ln3_b     = (const float*)d_in[16];
    const float* geglu_w   = (const float*)d_in[17];
    const float* geglu_b   = (const float*)d_in[18];
    const float* ffo_w     = (const float*)d_in[19];
    const float* ffo_b     = (const float*)d_in[20];
    float* out = (float*)d_out;
    long long E = (long long)in_sizes[1] / 2;

    float *p_h, *p_ln, *p_q, *p_xw, *p_ao, *p_k, *p_v, *p_u, *p_f;
    cudaGetSymbolAddress((void**)&p_h,  g_h);
    cudaGetSymbolAddress((void**)&p_ln, g_ln);
    cudaGetSymbolAddress((void**)&p_q,  g_q);
    cudaGetSymbolAddress((void**)&p_xw, g_xw);
    cudaGetSymbolAddress((void**)&p_ao, g_ao);
    cudaGetSymbolAddress((void**)&p_k,  g_k);
    cudaGetSymbolAddress((void**)&p_v,  g_v);
    cudaGetSymbolAddress((void**)&p_u,  g_u);
    cudaGetSymbolAddress((void**)&p_f,  g_f);

    cudaFuncSetAttribute(attn_kernel, cudaFuncAttributeMaxDynamicSharedMemorySize, ATTN_SMEM);

    init_kernel<<<64, 256>>>();
    detect_kernel<<<1, 256>>>((const unsigned int*)ei, (int)(E < 1024 ? E : 1024));
    bn_stats_kernel<<<128, 512>>>(x);
    bn_final_kernel<<<1, 512>>>(bn_w, bn_b);
    bn_apply_kernel<<<8192, 256>>>(x);                      // -> g_ln
    deg_kernel<<<512, 256>>>(ei, E);
    dinv_kernel<<<64, 256>>>();

    dim3 gs(8, 128);     // [16384,512] x [512,*512]
    dim3 gkv(8, 32);     // [4096,512]  x [512,512]
    dim3 gge(64, 128);   // [16384,4096] geglu

    gemm_kernel<false,false><<<gs, 256>>>(p_ln, gcn_in_w, nullptr, p_xw, NN, DD, DD);
    gcn_init_kernel<false><<<8192, 256>>>(gcn_in_b, nullptr, p_h);
    gcn_scatter_kernel<<<(unsigned)E, 128>>>(ei, E, p_xw, p_h);

    for (int i = 0; i < LL; i++) {
        ln_kernel<<<NN, 128>>>(p_h, ln2_w + i*DD, ln2_b + i*DD, p_ln);
        gemm_kernel<false,false><<<gs,  256>>>(p_ln, Wq + (size_t)i*DD*DD, nullptr, p_q, NN, DD, DD);
        gemm_kernel<false,false><<<gkv, 256>>>(cond, Wk + (size_t)i*DD*DD, nullptr, p_k, BSZ*MM, DD, DD);
        gemm_kernel<false,false><<<gkv, 256>>>(cond, Wv + (size_t)i*DD*DD, nullptr, p_v, BSZ*MM, DD, DD);
        attn_kernel<<<1024, 256, ATTN_SMEM>>>(p_q, p_k, p_v, p_ao);
        gemm_kernel<true,false><<<gs, 256>>>(p_ao, Wo + (size_t)i*DD*DD, nullptr, p_h, NN, DD, DD);
        ln_kernel<<<NN, 128>>>(p_h, ln3_w + i*DD, ln3_b + i*DD, p_ln);
        gemm_kernel<false,true><<<gge, 256>>>(p_ln, geglu_w + (size_t)i*DD*4096,
                                              geglu_b + (size_t)i*4096, p_u, NN, 4096, DD);
        geglu_kernel<<<32768, 256>>>();
        gemm_kernel<true,true><<<gs, 256>>>(p_f, ffo_w + (size_t)i*2048*DD,
                                            ffo_b + (size_t)i*DD, p_h, NN, DD, 2048);
    }

    gemm_kernel<false,false><<<gs, 256>>>(p_h, gcn_out_w, nullptr, p_xw, NN, DD, DD);
    gcn_init_kernel<true><<<8192, 256>>>(gcn_out_b, x, out);
    gcn_scatter_kernel<<<(unsigned)E, 128>>>(ei, E, p_xw, out);
}

// round 2
// speedup vs baseline: 2.0467x; 2.0467x over previous
#include <cuda_runtime.h>
#include <math.h>

// Problem constants
#define NN   16384
#define DD   512
#define BSZ  16
#define MM   256
#define LL   4

// ---------------- scratch (device globals; no allocs allowed) ----------------
__device__ float g_h [NN*DD];
__device__ float g_ln[NN*DD];
__device__ float g_q [NN*DD];
__device__ float g_xw[NN*DD];
__device__ float g_ao[NN*DD];
__device__ float g_k [BSZ*MM*DD];
__device__ float g_v [BSZ*MM*DD];
__device__ float g_u [(size_t)NN*4096];
__device__ float g_f [(size_t)NN*2048];
__device__ float g_mu[DD];
__device__ float g_var[DD];
__device__ float g_scale[DD];
__device__ float g_shift[DD];
__device__ float g_deg [NN];
__device__ float g_dinv[NN];
__device__ int   g_is64;

// ---------------- helpers ----------------
__device__ __forceinline__ int edge_at(const void* ei, long long pos) {
    if (g_is64) return (int)((const long long*)ei)[pos];
    return ((const int*)ei)[pos];
}

__device__ __forceinline__ float gelu_exact(float x) {
    return 0.5f * x * (1.0f + erff(x * 0.70710678118654752f));
}

__device__ __forceinline__ unsigned f2tf32(float x) {
    unsigned y;
    asm("cvt.rna.tf32.f32 %0, %1;" : "=r"(y) : "f"(x));
    return y;
}

__device__ __forceinline__ void cp_async16(void* smem, const void* gmem) {
    unsigned s = (unsigned)__cvta_generic_to_shared(smem);
    asm volatile("cp.async.cg.shared.global [%0], [%1], 16;\n" :: "r"(s), "l"(gmem));
}
#define CP_COMMIT() asm volatile("cp.async.commit_group;\n" ::)
#define CP_WAIT0()  asm volatile("cp.async.wait_group 0;\n" ::)

__device__ __forceinline__ void mma_tf32(float* d, const unsigned* a, const unsigned* b) {
    asm volatile(
      "mma.sync.aligned.m16n8k8.row.col.f32.tf32.tf32.f32 "
      "{%0,%1,%2,%3}, {%4,%5,%6,%7}, {%8,%9}, {%0,%1,%2,%3};\n"
      : "+f"(d[0]), "+f"(d[1]), "+f"(d[2]), "+f"(d[3])
      : "r"(a[0]), "r"(a[1]), "r"(a[2]), "r"(a[3]), "r"(b[0]), "r"(b[1]));
}

// ---------------- init ----------------
__global__ void init_kernel() {
    int i = blockIdx.x * blockDim.x + threadIdx.x;
    if (i < NN) g_deg[i] = 1.0f;
    if (i < DD) { g_mu[i] = 0.0f; g_var[i] = 0.0f; }
}

// ---------------- edge-index dtype sniffer ----------------
__global__ void detect_kernel(const unsigned int* __restrict__ raw, int n) {
    __shared__ int any;
    if (threadIdx.x == 0) any = 0;
    __syncthreads();
    int local = 0;
    for (int j = threadIdx.x; j < n; j += blockDim.x)
        if (raw[2*j + 1] != 0u) local = 1;
    if (local) atomicOr(&any, 1);
    __syncthreads();
    if (threadIdx.x == 0) g_is64 = any ? 0 : 1;
}

// ---------------- BatchNorm ----------------
__global__ void bn_stats_kernel(const float* __restrict__ x) {
    int c = threadIdx.x;
    size_t r0 = (size_t)blockIdx.x * 128;
    float s = 0.f, sq = 0.f;
    for (int r = 0; r < 128; r++) {
        float v = x[(r0 + r) * DD + c];
        s += v; sq += v * v;
    }
    atomicAdd(&g_mu[c], s);
    atomicAdd(&g_var[c], sq);
}

__global__ void bn_final_kernel(const float* __restrict__ w, const float* __restrict__ b) {
    int c = threadIdx.x;
    float mu  = g_mu[c]  * (1.0f / NN);
    float var = g_var[c] * (1.0f / NN) - mu * mu;
    float sc  = w[c] * rsqrtf(var + 1e-5f);
    g_scale[c] = sc;
    g_shift[c] = b[c] - mu * sc;
}

__global__ void bn_apply_kernel(const float* __restrict__ x) {
    size_t idx = (size_t)blockIdx.x * blockDim.x + threadIdx.x;
    int c4 = (int)(idx & 127);
    float4 xv = ((const float4*)x)[idx];
    float4 sc = ((const float4*)g_scale)[c4];
    float4 sh = ((const float4*)g_shift)[c4];
    float4 r;
    r.x = xv.x * sc.x + sh.x; r.y = xv.y * sc.y + sh.y;
    r.z = xv.z * sc.z + sh.z; r.w = xv.w * sc.w + sh.w;
    ((float4*)g_ln)[idx] = r;
}

// ---------------- GCN degree / dinv ----------------
__global__ void deg_kernel(const void* __restrict__ ei, long long E) {
    long long stride = (long long)gridDim.x * blockDim.x;
    for (long long e = (long long)blockIdx.x * blockDim.x + threadIdx.x; e < E; e += stride) {
        int d = edge_at(ei, E + e);
        atomicAdd(&g_deg[d], 1.0f);
    }
}

__global__ void dinv_kernel() {
    int i = blockIdx.x * blockDim.x + threadIdx.x;
    if (i < NN) g_dinv[i] = rsqrtf(g_deg[i]);
}

template<bool ADDX>
__global__ void gcn_init_kernel(const float* __restrict__ bias,
                                const float* __restrict__ xin,
                                float* __restrict__ dst) {
    size_t idx = (size_t)blockIdx.x * blockDim.x + threadIdx.x;
    size_t row = idx >> 7;
    int c4 = (int)(idx & 127);
    float d2 = g_dinv[row]; d2 *= d2;
    float4 xw = ((const float4*)g_xw)[idx];
    float4 bb = ((const float4*)bias)[c4];
    float4 r;
    r.x = bb.x + d2 * xw.x; r.y = bb.y + d2 * xw.y;
    r.z = bb.z + d2 * xw.z; r.w = bb.w + d2 * xw.w;
    if (ADDX) {
        float4 xv = ((const float4*)xin)[idx];
        r.x += xv.x; r.y += xv.y; r.z += xv.z; r.w += xv.w;
    }
    ((float4*)dst)[idx] = r;
}

__global__ void gcn_scatter_kernel(const void* __restrict__ ei, long long E,
                                   const float* __restrict__ xw, float* __restrict__ dst) {
    long long e = blockIdx.x;
    int s = edge_at(ei, e);
    int d = edge_at(ei, E + e);
    float norm = g_dinv[s] * g_dinv[d];
    const float4* sp = (const float4*)(xw + (size_t)s * DD);
    float* dp = dst + (size_t)d * DD;
    int c = threadIdx.x;
    float4 v = sp[c];
    atomicAdd(&dp[c*4 + 0], v.x * norm);
    atomicAdd(&dp[c*4 + 1], v.y * norm);
    atomicAdd(&dp[c*4 + 2], v.z * norm);
    atomicAdd(&dp[c*4 + 3], v.w * norm);
}

// ---------------- LayerNorm ----------------
__global__ void ln_kernel(const float* __restrict__ x, const float* __restrict__ w,
                          const float* __restrict__ b, float* __restrict__ y) {
    __shared__ float red[8];
    size_t row = blockIdx.x;
    int t = threadIdx.x;
    float4 v = ((const float4*)(x + row * DD))[t];
    float s  = v.x + v.y + v.z + v.w;
    float sq = v.x*v.x + v.y*v.y + v.z*v.z + v.w*v.w;
    for (int o = 16; o; o >>= 1) {
        s  += __shfl_xor_sync(0xffffffffu, s,  o);
        sq += __shfl_xor_sync(0xffffffffu, sq, o);
    }
    if ((t & 31) == 0) { red[t >> 5] = s; red[4 + (t >> 5)] = sq; }
    __syncthreads();
    s  = red[0] + red[1] + red[2] + red[3];
    sq = red[4] + red[5] + red[6] + red[7];
    float mean = s * (1.0f / DD);
    float var  = sq * (1.0f / DD) - mean * mean;
    float rstd = rsqrtf(var + 1e-5f);
    float4 wv = ((const float4*)w)[t];
    float4 bv = ((const float4*)b)[t];
    float4 o4;
    o4.x = (v.x - mean) * rstd * wv.x + bv.x;
    o4.y = (v.y - mean) * rstd * wv.y + bv.y;
    o4.z = (v.z - mean) * rstd * wv.z + bv.z;
    o4.w = (v.w - mean) * rstd * wv.w + bv.w;
    ((float4*)(y + row * DD))[t] = o4;
}

// ---------------- tf32 tensor-core GEMM ----------------
// C[M,N] (+)= A[M,K] @ B[K,N] (+ bias). Block tile 128x128x32, 256 threads,
// 8 warps in 2x4 grid, warp tile 64x32, mma.m16n8k8.tf32, cp.async 2-stage.
#define GBM 128
#define GBN 128
#define GBK 32
#define ASTRIDE 36     // 32 + 4 pad (floats)
#define BSTRIDE 136    // 128 + 8 pad (floats)
#define A_BUF (GBM * ASTRIDE)
#define B_BUF (GBK * BSTRIDE)
#define GEMM_SMEM ((2 * A_BUF + 2 * B_BUF) * 4)

template<bool ACCUM, bool BIAS>
__global__ void __launch_bounds__(256) mma_gemm_kernel(
    const float* __restrict__ A, const float* __restrict__ B,
    const float* __restrict__ bias, float* __restrict__ C,
    int Ndim, int Kdim)
{
    extern __shared__ float sm[];
    float* As = sm;                  // [2][128][36]
    float* Bs = sm + 2 * A_BUF;      // [2][32][136]

    int tid  = threadIdx.x;
    int warp = tid >> 5, lane = tid & 31;
    int wm = warp & 1, wn = warp >> 1;     // 2 x 4 warps
    int g  = lane >> 2, tg = lane & 3;
    int row0 = blockIdx.y * GBM;
    int col0 = blockIdx.x * GBN;

    float acc[4][4][4];
#pragma unroll
    for (int i = 0; i < 4; i++)
#pragma unroll
        for (int j = 0; j < 4; j++)
#pragma unroll
            for (int r = 0; r < 4; r++) acc[i][j][r] = 0.f;

    // A load map: 1024 float4, 4 per thread. f -> (r = f>>3, c4 = f&7)
    // B load map: 1024 float4, 4 per thread. f -> (r = f>>5, c4 = f&31)
    auto load_tiles = [&](int buf, int k0) {
#pragma unroll
        for (int i = 0; i < 4; i++) {
            int f = tid + 256 * i;
            int r = f >> 3, c4 = f & 7;
            cp_async16(&As[buf * A_BUF + r * ASTRIDE + c4 * 4],
                       A + (size_t)(row0 + r) * Kdim + k0 + c4 * 4);
        }
#pragma unroll
        for (int i = 0; i < 4; i++) {
            int f = tid + 256 * i;
            int r = f >> 5, c4 = f & 31;
            cp_async16(&Bs[buf * B_BUF + r * BSTRIDE + c4 * 4],
                       B + (size_t)(k0 + r) * Ndim + col0 + c4 * 4);
        }
    };

    int nk = Kdim / GBK;
    load_tiles(0, 0);
    CP_COMMIT();

    int buf = 0;
    for (int t = 0; t < nk; t++) {
        CP_WAIT0();
        __syncthreads();
        if (t + 1 < nk) {
            load_tiles(buf ^ 1, (t + 1) * GBK);
            CP_COMMIT();
        }
        const float* Ab = &As[buf * A_BUF];
        const float* Bb = &Bs[buf * B_BUF];
#pragma unroll
        for (int kk = 0; kk < 4; kk++) {
            int kb = kk * 8;
            unsigned af[4][4], bf[4][2];
#pragma unroll
            for (int i = 0; i < 4; i++) {
                const float* ap = Ab + (wm * 64 + i * 16 + g) * ASTRIDE + kb + tg;
                af[i][0] = f2tf32(ap[0]);
                af[i][1] = f2tf32(ap[8 * ASTRIDE]);
                af[i][2] = f2tf32(ap[4]);
                af[i][3] = f2tf32(ap[8 * ASTRIDE + 4]);
            }
#pragma unroll
            for (int j = 0; j < 4; j++) {
                const float* bp = Bb + (kb + tg) * BSTRIDE + wn * 32 + j * 8 + g;
                bf[j][0] = f2tf32(bp[0]);
                bf[j][1] = f2tf32(bp[4 * BSTRIDE]);
            }
#pragma unroll
            for (int i = 0; i < 4; i++)
#pragma unroll
                for (int j = 0; j < 4; j++)
                    mma_tf32(acc[i][j], af[i], bf[j]);
        }
        buf ^= 1;
    }

    // epilogue: each thread owns rows (g, g+8) x cols (tg*2, tg*2+1) per tile
#pragma unroll
    for (int i = 0; i < 4; i++) {
        int r = row0 + wm * 64 + i * 16 + g;
#pragma unroll
        for (int j = 0; j < 4; j++) {
            int c = col0 + wn * 32 + j * 8 + tg * 2;
            float2 v0 = make_float2(acc[i][j][0], acc[i][j][1]);
            float2 v1 = make_float2(acc[i][j][2], acc[i][j][3]);
            if (BIAS) {
                float2 bb = *(const float2*)(bias + c);
                v0.x += bb.x; v0.y += bb.y;
                v1.x += bb.x; v1.y += bb.y;
            }
            size_t o0 = (size_t)r * Ndim + c;
            size_t o1 = (size_t)(r + 8) * Ndim + c;
            if (ACCUM) {
                float2 e0 = *(const float2*)(C + o0);
                float2 e1 = *(const float2*)(C + o1);
                v0.x += e0.x; v0.y += e0.y;
                v1.x += e1.x; v1.y += e1.y;
            }
            *(float2*)(C + o0) = v0;
            *(float2*)(C + o1) = v1;
        }
    }
}

// ---------------- fused attention ----------------
#define ATTN_SMEM ((2*256*65 + 8*256 + 8*64) * 4)

__global__ void attn_kernel(const float* __restrict__ q, const float* __restrict__ k,
                            const float* __restrict__ v, float* __restrict__ o)
{
    extern __shared__ float sm[];
    float* Ks = sm;
    float* Vs = sm + 256*65;
    float* Ps = Vs + 256*65;
    float* Qs = Ps + 8*256;
    int chunk = blockIdx.x & 7;
    int hh    = (blockIdx.x >> 3) & 7;
    int b     = blockIdx.x >> 6;
    int tid = threadIdx.x;
    int w = tid >> 5, l = tid & 31;

    for (int j = tid; j < 256*16; j += 256) {
        int m = j >> 4, f = j & 15;
        size_t gg = (size_t)(b*256 + m) * DD + hh*64 + f*4;
        float4 kv = *(const float4*)(k + gg);
        float4 vv = *(const float4*)(v + gg);
        float* kd = &Ks[m*65 + f*4];
        kd[0] = kv.x; kd[1] = kv.y; kd[2] = kv.z; kd[3] = kv.w;
        float* vd = &Vs[m*65 + f*4];
        vd[0] = vv.x; vd[1] = vv.y; vd[2] = vv.z; vd[3] = vv.w;
    }
    __syncthreads();

    float* myP = Ps + w*256;
    float* myQ = Qs + w*64;
    for (int qi = w; qi < 128; qi += 8) {
        size_t qoff = ((size_t)b*1024 + chunk*128 + qi) * DD + hh*64;
        myQ[l]      = q[qoff + l]      * 0.125f;
        myQ[l + 32] = q[qoff + l + 32] * 0.125f;
        __syncwarp();
        float s[8];
#pragma unroll
        for (int t = 0; t < 8; t++) s[t] = 0.f;
        for (int d = 0; d < 64; d++) {
            float qd = myQ[d];
#pragma unroll
            for (int t = 0; t < 8; t++) s[t] += qd * Ks[(l + 32*t)*65 + d];
        }
        float mx = s[0];
#pragma unroll
        for (int t = 1; t < 8; t++) mx = fmaxf(mx, s[t]);
        for (int off = 16; off; off >>= 1) mx = fmaxf(mx, __shfl_xor_sync(0xffffffffu, mx, off));
        float sum = 0.f;
#pragma unroll
        for (int t = 0; t < 8; t++) { s[t] = __expf(s[t] - mx); sum += s[t]; }
        for (int off = 16; off; off >>= 1) sum += __shfl_xor_sync(0xffffffffu, sum, off);
        float inv = 1.0f / sum;
#pragma unroll
        for (int t = 0; t < 8; t++) myP[l + 32*t] = s[t] * inv;
        __syncwarp();
        float o0 = 0.f, o1 = 0.f;
#pragma unroll 4
        for (int j = 0; j < 256; j++) {
            float p = myP[j];
            o0 += p * Vs[j*65 + l];
            o1 += p * Vs[j*65 + l + 32];
        }
        o[qoff + l]      = o0;
        o[qoff + l + 32] = o1;
        __syncwarp();
    }
}

// ---------------- GEGLU elementwise ----------------
__global__ void geglu_kernel() {
    size_t idx = (size_t)blockIdx.x * blockDim.x + threadIdx.x;
    size_t row = idx >> 9;
    int c4 = (int)(idx & 511);
    float4 val = ((const float4*)g_u)[row*1024 + c4];
    float4 gt  = ((const float4*)g_u)[row*1024 + 512 + c4];
    float4 r;
    r.x = val.x * gelu_exact(gt.x);
    r.y = val.y * gelu_exact(gt.y);
    r.z = val.z * gelu_exact(gt.z);
    r.w = val.w * gelu_exact(gt.w);
    ((float4*)g_f)[idx] = r;
}

// ---------------- launch ----------------
extern "C" void kernel_launch(void* const* d_in, const int* in_sizes, int n_in,
                              void* d_out, int out_size)
{
    const float* x         = (const float*)d_in[0];
    const void*  ei        = d_in[1];
    const float* cond      = (const float*)d_in[2];
    const float* bn_w      = (const float*)d_in[3];
    const float* bn_b      = (const float*)d_in[4];
    const float* gcn_in_w  = (const float*)d_in[5];
    const float* gcn_in_b  = (const float*)d_in[6];
    const float* gcn_out_w = (const float*)d_in[7];
    const float* gcn_out_b = (const float*)d_in[8];
    const float* Wq        = (const float*)d_in[9];
    const float* Wk        = (const float*)d_in[10];
    const float* Wv        = (const float*)d_in[11];
    const float* Wo        = (const float*)d_in[12];
    const float* ln2_w     = (const float*)d_in[13];
    const float* ln2_b     = (const float*)d_in[14];
    const float* ln3_w     = (const float*)d_in[15];
    const float* ln3_b     = (const float*)d_in[16];
    const float* geglu_w   = (const float*)d_in[17];
    const float* geglu_b   = (const float*)d_in[18];
    const float* ffo_w     = (const float*)d_in[19];
    const float* ffo_b     = (const float*)d_in[20];
    float* out = (float*)d_out;
    long long E = (long long)in_sizes[1] / 2;

    float *p_h, *p_ln, *p_q, *p_xw, *p_ao, *p_k, *p_v, *p_u, *p_f;
    cudaGetSymbolAddress((void**)&p_h,  g_h);
    cudaGetSymbolAddress((void**)&p_ln, g_ln);
    cudaGetSymbolAddress((void**)&p_q,  g_q);
    cudaGetSymbolAddress((void**)&p_xw, g_xw);
    cudaGetSymbolAddress((void**)&p_ao, g_ao);
    cudaGetSymbolAddress((void**)&p_k,  g_k);
    cudaGetSymbolAddress((void**)&p_v,  g_v);
    cudaGetSymbolAddress((void**)&p_u,  g_u);
    cudaGetSymbolAddress((void**)&p_f,  g_f);

    cudaFuncSetAttribute(attn_kernel, cudaFuncAttributeMaxDynamicSharedMemorySize, ATTN_SMEM);
    cudaFuncSetAttribute(mma_gemm_kernel<false,false>, cudaFuncAttributeMaxDynamicSharedMemorySize, GEMM_SMEM);
    cudaFuncSetAttribute(mma_gemm_kernel<true,false>,  cudaFuncAttributeMaxDynamicSharedMemorySize, GEMM_SMEM);
    cudaFuncSetAttribute(mma_gemm_kernel<false,true>,  cudaFuncAttributeMaxDynamicSharedMemorySize, GEMM_SMEM);
    cudaFuncSetAttribute(mma_gemm_kernel<true,true>,   cudaFuncAttributeMaxDynamicSharedMemorySize, GEMM_SMEM);

    init_kernel<<<64, 256>>>();
    detect_kernel<<<1, 256>>>((const unsigned int*)ei, (int)(E < 1024 ? E : 1024));
    bn_stats_kernel<<<128, 512>>>(x);
    bn_final_kernel<<<1, 512>>>(bn_w, bn_b);
    bn_apply_kernel<<<8192, 256>>>(x);                      // -> g_ln
    deg_kernel<<<512, 256>>>(ei, E);
    dinv_kernel<<<64, 256>>>();

    dim3 g512(4, 128);   // [16384,512]
    dim3 gkv(4, 32);     // [4096,512]
    dim3 gge(32, 128);   // [16384,4096]

    mma_gemm_kernel<false,false><<<g512, 256, GEMM_SMEM>>>(p_ln, gcn_in_w, nullptr, p_xw, DD, DD);
    gcn_init_kernel<false><<<8192, 256>>>(gcn_in_b, nullptr, p_h);
    gcn_scatter_kernel<<<(unsigned)E, 128>>>(ei, E, p_xw, p_h);

    for (int i = 0; i < LL; i++) {
        ln_kernel<<<NN, 128>>>(p_h, ln2_w + i*DD, ln2_b + i*DD, p_ln);
        mma_gemm_kernel<false,false><<<g512, 256, GEMM_SMEM>>>(p_ln, Wq + (size_t)i*DD*DD, nullptr, p_q, DD, DD);
        mma_gemm_kernel<false,false><<<gkv,  256, GEMM_SMEM>>>(cond, Wk + (size_t)i*DD*DD, nullptr, p_k, DD, DD);
        mma_gemm_kernel<false,false><<<gkv,  256, GEMM_SMEM>>>(cond, Wv + (size_t)i*DD*DD, nullptr, p_v, DD, DD);
        attn_kernel<<<1024, 256, ATTN_SMEM>>>(p_q, p_k, p_v, p_ao);
        mma_gemm_kernel<true,false><<<g512, 256, GEMM_SMEM>>>(p_ao, Wo + (size_t)i*DD*DD, nullptr, p_h, DD, DD);
        ln_kernel<<<NN, 128>>>(p_h, ln3_w + i*DD, ln3_b + i*DD, p_ln);
        mma_gemm_kernel<false,true><<<gge, 256, GEMM_SMEM>>>(p_ln, geglu_w + (size_t)i*DD*4096,
                                                             geglu_b + (size_t)i*4096, p_u, 4096, DD);
        geglu_kernel<<<32768, 256>>>();
        mma_gemm_kernel<true,true><<<g512, 256, GEMM_SMEM>>>(p_f, ffo_w + (size_t)i*2048*DD,
                                                             ffo_b + (size_t)i*DD, p_h, DD, 2048);
    }

    mma_gemm_kernel<false,false><<<g512, 256, GEMM_SMEM>>>(p_h, gcn_out_w, nullptr, p_xw, DD, DD);
    gcn_init_kernel<true><<<8192, 256>>>(gcn_out_b, x, out);
    gcn_scatter_kernel<<<(unsigned)E, 128>>>(ei, E, p_xw, out);
}

// round 3
// speedup vs baseline: 2.3611x; 1.1536x over previous
#include <cuda_runtime.h>
#include <math.h>

// Problem constants
#define NN   16384
#define DD   512
#define BSZ  16
#define MM   256
#define LL   4
#define EE   262144

// ---------------- scratch (device globals; no allocs allowed) ----------------
__device__ float g_h [NN*DD];
__device__ float g_ln[NN*DD];
__device__ float g_q [NN*DD];
__device__ float g_xw[NN*DD];
__device__ float g_ao[NN*DD];
__device__ float g_k [BSZ*MM*DD];
__device__ float g_v [BSZ*MM*DD];
__device__ float g_f [(size_t)NN*2048];
__device__ float g_mu[DD];
__device__ float g_var[DD];
__device__ float g_scale[DD];
__device__ float g_shift[DD];
__device__ float g_dinv[NN];
__device__ int   g_count[NN];
__device__ int   g_cur[NN];
__device__ int   g_rowptr[NN+1];
__device__ int   g_srcs[EE];
__device__ int   g_is64;

// ---------------- helpers ----------------
__device__ __forceinline__ int edge_at(const void* ei, long long pos) {
    if (g_is64) return (int)((const long long*)ei)[pos];
    return ((const int*)ei)[pos];
}

__device__ __forceinline__ float gelu_exact(float x) {
    return 0.5f * x * (1.0f + erff(x * 0.70710678118654752f));
}

__device__ __forceinline__ unsigned f2tf32(float x) {
    unsigned y;
    asm("cvt.rna.tf32.f32 %0, %1;" : "=r"(y) : "f"(x));
    return y;
}

__device__ __forceinline__ void cp_async16(void* smem, const void* gmem) {
    unsigned s = (unsigned)__cvta_generic_to_shared(smem);
    asm volatile("cp.async.cg.shared.global [%0], [%1], 16;\n" :: "r"(s), "l"(gmem));
}
#define CP_COMMIT() asm volatile("cp.async.commit_group;\n" ::)
#define CP_WAIT0()  asm volatile("cp.async.wait_group 0;\n" ::)

__device__ __forceinline__ void mma_tf32(float* d, const unsigned* a, const unsigned* b) {
    asm volatile(
      "mma.sync.aligned.m16n8k8.row.col.f32.tf32.tf32.f32 "
      "{%0,%1,%2,%3}, {%4,%5,%6,%7}, {%8,%9}, {%0,%1,%2,%3};\n"
      : "+f"(d[0]), "+f"(d[1]), "+f"(d[2]), "+f"(d[3])
      : "r"(a[0]), "r"(a[1]), "r"(a[2]), "r"(a[3]), "r"(b[0]), "r"(b[1]));
}

// ---------------- init ----------------
__global__ void init_kernel() {
    int i = blockIdx.x * blockDim.x + threadIdx.x;
    if (i < NN) g_count[i] = 0;
    if (i < DD) { g_mu[i] = 0.0f; g_var[i] = 0.0f; }
}

// ---------------- edge-index dtype sniffer ----------------
__global__ void detect_kernel(const unsigned int* __restrict__ raw, int n) {
    __shared__ int any;
    if (threadIdx.x == 0) any = 0;
    __syncthreads();
    int local = 0;
    for (int j = threadIdx.x; j < n; j += blockDim.x)
        if (raw[2*j + 1] != 0u) local = 1;
    if (local) atomicOr(&any, 1);
    __syncthreads();
    if (threadIdx.x == 0) g_is64 = any ? 0 : 1;
}

// ---------------- BatchNorm ----------------
__global__ void bn_stats_kernel(const float* __restrict__ x) {
    int c = threadIdx.x;
    size_t r0 = (size_t)blockIdx.x * 128;
    float s = 0.f, sq = 0.f;
    for (int r = 0; r < 128; r++) {
        float v = x[(r0 + r) * DD + c];
        s += v; sq += v * v;
    }
    atomicAdd(&g_mu[c], s);
    atomicAdd(&g_var[c], sq);
}

__global__ void bn_final_kernel(const float* __restrict__ w, const float* __restrict__ b) {
    int c = threadIdx.x;
    float mu  = g_mu[c]  * (1.0f / NN);
    float var = g_var[c] * (1.0f / NN) - mu * mu;
    float sc  = w[c] * rsqrtf(var + 1e-5f);
    g_scale[c] = sc;
    g_shift[c] = b[c] - mu * sc;
}

__global__ void bn_apply_kernel(const float* __restrict__ x) {
    size_t idx = (size_t)blockIdx.x * blockDim.x + threadIdx.x;
    int c4 = (int)(idx & 127);
    float4 xv = ((const float4*)x)[idx];
    float4 sc = ((const float4*)g_scale)[c4];
    float4 sh = ((const float4*)g_shift)[c4];
    float4 r;
    r.x = xv.x * sc.x + sh.x; r.y = xv.y * sc.y + sh.y;
    r.z = xv.z * sc.z + sh.z; r.w = xv.w * sc.w + sh.w;
    ((float4*)g_ln)[idx] = r;
}

// ---------------- CSR build ----------------
__global__ void hist_kernel(const void* __restrict__ ei, long long E) {
    long long stride = (long long)gridDim.x * blockDim.x;
    for (long long e = (long long)blockIdx.x * blockDim.x + threadIdx.x; e < E; e += stride) {
        int d = edge_at(ei, E + e);
        atomicAdd(&g_count[d], 1);
    }
}

__global__ void scan_kernel() {   // 1 block, 1024 threads; NN = 1024*16
    __shared__ int part[1024];
    int t = threadIdx.x;
    int base = t * 16;
    int loc[16];
    int s = 0;
#pragma unroll
    for (int j = 0; j < 16; j++) { loc[j] = g_count[base + j]; s += loc[j]; }
    part[t] = s;
    __syncthreads();
    for (int off = 1; off < 1024; off <<= 1) {
        int v = (t >= off) ? part[t - off] : 0;
        __syncthreads();
        part[t] += v;
        __syncthreads();
    }
    int run = part[t] - s;  // exclusive prefix
#pragma unroll
    for (int j = 0; j < 16; j++) {
        g_rowptr[base + j] = run;
        run += loc[j];
        g_cur[base + j] = 0;
        g_dinv[base + j] = rsqrtf((float)loc[j] + 1.0f);   // +1 self loop
    }
    if (t == 1023) g_rowptr[NN] = part[1023];
}

__global__ void fill_kernel(const void* __restrict__ ei, long long E) {
    long long stride = (long long)gridDim.x * blockDim.x;
    for (long long e = (long long)blockIdx.x * blockDim.x + threadIdx.x; e < E; e += stride) {
        int s = edge_at(ei, e);
        int d = edge_at(ei, E + e);
        int pos = g_rowptr[d] + atomicAdd(&g_cur[d], 1);
        g_srcs[pos] = s;
    }
}

// ---------------- GCN gather: dst[n] = bias + sum_e norm * xw[src] (+x) ----------------
template<bool ADDX>
__global__ void gcn_gather_kernel(const float* __restrict__ bias,
                                  const float* __restrict__ xin,
                                  float* __restrict__ dst) {
    int n = blockIdx.x;
    int c = threadIdx.x;   // 128 threads, one float4 each
    const float4* xw4 = (const float4*)g_xw;
    float di = g_dinv[n];
    float4 acc = ((const float4*)bias)[c];
    float4 sf = xw4[(size_t)n * 128 + c];
    float d2 = di * di;
    acc.x += d2 * sf.x; acc.y += d2 * sf.y; acc.z += d2 * sf.z; acc.w += d2 * sf.w;
    int e = g_rowptr[n], end = g_rowptr[n + 1];
    for (; e + 4 <= end; e += 4) {
        int s0 = g_srcs[e], s1 = g_srcs[e+1], s2 = g_srcs[e+2], s3 = g_srcs[e+3];
        float n0 = di * g_dinv[s0], n1 = di * g_dinv[s1];
        float n2 = di * g_dinv[s2], n3 = di * g_dinv[s3];
        float4 v0 = xw4[(size_t)s0 * 128 + c];
        float4 v1 = xw4[(size_t)s1 * 128 + c];
        float4 v2 = xw4[(size_t)s2 * 128 + c];
        float4 v3 = xw4[(size_t)s3 * 128 + c];
        acc.x += n0*v0.x + n1*v1.x + n2*v2.x + n3*v3.x;
        acc.y += n0*v0.y + n1*v1.y + n2*v2.y + n3*v3.y;
        acc.z += n0*v0.z + n1*v1.z + n2*v2.z + n3*v3.z;
        acc.w += n0*v0.w + n1*v1.w + n2*v2.w + n3*v3.w;
    }
    for (; e < end; e++) {
        int s0 = g_srcs[e];
        float n0 = di * g_dinv[s0];
        float4 v0 = xw4[(size_t)s0 * 128 + c];
        acc.x += n0*v0.x; acc.y += n0*v0.y; acc.z += n0*v0.z; acc.w += n0*v0.w;
    }
    if (ADDX) {
        float4 xv = ((const float4*)xin)[(size_t)n * 128 + c];
        acc.x += xv.x; acc.y += xv.y; acc.z += xv.z; acc.w += xv.w;
    }
    ((float4*)dst)[(size_t)n * 128 + c] = acc;
}

// ---------------- LayerNorm ----------------
__global__ void ln_kernel(const float* __restrict__ x, const float* __restrict__ w,
                          const float* __restrict__ b, float* __restrict__ y) {
    __shared__ float red[8];
    size_t row = blockIdx.x;
    int t = threadIdx.x;
    float4 v = ((const float4*)(x + row * DD))[t];
    float s  = v.x + v.y + v.z + v.w;
    float sq = v.x*v.x + v.y*v.y + v.z*v.z + v.w*v.w;
    for (int o = 16; o; o >>= 1) {
        s  += __shfl_xor_sync(0xffffffffu, s,  o);
        sq += __shfl_xor_sync(0xffffffffu, sq, o);
    }
    if ((t & 31) == 0) { red[t >> 5] = s; red[4 + (t >> 5)] = sq; }
    __syncthreads();
    s  = red[0] + red[1] + red[2] + red[3];
    sq = red[4] + red[5] + red[6] + red[7];
    float mean = s * (1.0f / DD);
    float var  = sq * (1.0f / DD) - mean * mean;
    float rstd = rsqrtf(var + 1e-5f);
    float4 wv = ((const float4*)w)[t];
    float4 bv = ((const float4*)b)[t];
    float4 o4;
    o4.x = (v.x - mean) * rstd * wv.x + bv.x;
    o4.y = (v.y - mean) * rstd * wv.y + bv.y;
    o4.z = (v.z - mean) * rstd * wv.z + bv.z;
    o4.w = (v.w - mean) * rstd * wv.w + bv.w;
    ((float4*)(y + row * DD))[t] = o4;
}

// ---------------- tf32 tensor-core GEMM ----------------
#define GBM 128
#define GBN 128
#define GBK 32
#define ASTRIDE 36
#define BSTRIDE 136
#define A_BUF (GBM * ASTRIDE)
#define B_BUF (GBK * BSTRIDE)
#define GEMM_SMEM ((2 * A_BUF + 2 * B_BUF) * 4)

template<bool ACCUM, bool BIAS>
__global__ void __launch_bounds__(256) mma_gemm_kernel(
    const float* __restrict__ A, const float* __restrict__ B,
    const float* __restrict__ bias, float* __restrict__ C,
    int Ndim, int Kdim)
{
    extern __shared__ float sm[];
    float* As = sm;
    float* Bs = sm + 2 * A_BUF;

    int tid  = threadIdx.x;
    int warp = tid >> 5, lane = tid & 31;
    int wm = warp & 1, wn = warp >> 1;
    int g  = lane >> 2, tg = lane & 3;
    int row0 = blockIdx.y * GBM;
    int col0 = blockIdx.x * GBN;

    float acc[4][4][4];
#pragma unroll
    for (int i = 0; i < 4; i++)
#pragma unroll
        for (int j = 0; j < 4; j++)
#pragma unroll
            for (int r = 0; r < 4; r++) acc[i][j][r] = 0.f;

    auto load_tiles = [&](int buf, int k0) {
#pragma unroll
        for (int i = 0; i < 4; i++) {
            int f = tid + 256 * i;
            int r = f >> 3, c4 = f & 7;
            cp_async16(&As[buf * A_BUF + r * ASTRIDE + c4 * 4],
                       A + (size_t)(row0 + r) * Kdim + k0 + c4 * 4);
        }
#pragma unroll
        for (int i = 0; i < 4; i++) {
            int f = tid + 256 * i;
            int r = f >> 5, c4 = f & 31;
            cp_async16(&Bs[buf * B_BUF + r * BSTRIDE + c4 * 4],
                       B + (size_t)(k0 + r) * Ndim + col0 + c4 * 4);
        }
    };

    int nk = Kdim / GBK;
    load_tiles(0, 0);
    CP_COMMIT();

    int buf = 0;
    for (int t = 0; t < nk; t++) {
        CP_WAIT0();
        __syncthreads();
        if (t + 1 < nk) {
            load_tiles(buf ^ 1, (t + 1) * GBK);
            CP_COMMIT();
        }
        const float* Ab = &As[buf * A_BUF];
        const float* Bb = &Bs[buf * B_BUF];
#pragma unroll
        for (int kk = 0; kk < 4; kk++) {
            int kb = kk * 8;
            unsigned af[4][4], bf[4][2];
#pragma unroll
            for (int i = 0; i < 4; i++) {
                const float* ap = Ab + (wm * 64 + i * 16 + g) * ASTRIDE + kb + tg;
                af[i][0] = f2tf32(ap[0]);
                af[i][1] = f2tf32(ap[8 * ASTRIDE]);
                af[i][2] = f2tf32(ap[4]);
                af[i][3] = f2tf32(ap[8 * ASTRIDE + 4]);
            }
#pragma unroll
            for (int j = 0; j < 4; j++) {
                const float* bp = Bb + (kb + tg) * BSTRIDE + wn * 32 + j * 8 + g;
                bf[j][0] = f2tf32(bp[0]);
                bf[j][1] = f2tf32(bp[4 * BSTRIDE]);
            }
#pragma unroll
            for (int i = 0; i < 4; i++)
#pragma unroll
                for (int j = 0; j < 4; j++)
                    mma_tf32(acc[i][j], af[i], bf[j]);
        }
        buf ^= 1;
    }

#pragma unroll
    for (int i = 0; i < 4; i++) {
        int r = row0 + wm * 64 + i * 16 + g;
#pragma unroll
        for (int j = 0; j < 4; j++) {
            int c = col0 + wn * 32 + j * 8 + tg * 2;
            float2 v0 = make_float2(acc[i][j][0], acc[i][j][1]);
            float2 v1 = make_float2(acc[i][j][2], acc[i][j][3]);
            if (BIAS) {
                float2 bb = *(const float2*)(bias + c);
                v0.x += bb.x; v0.y += bb.y;
                v1.x += bb.x; v1.y += bb.y;
            }
            size_t o0 = (size_t)r * Ndim + c;
            size_t o1 = (size_t)(r + 8) * Ndim + c;
            if (ACCUM) {
                float2 e0 = *(const float2*)(C + o0);
                float2 e1 = *(const float2*)(C + o1);
                v0.x += e0.x; v0.y += e0.y;
                v1.x += e1.x; v1.y += e1.y;
            }
            *(float2*)(C + o0) = v0;
            *(float2*)(C + o1) = v1;
        }
    }
}

// ---------------- fused GEGLU GEMM ----------------
// f[:, c] = (A@Wv + bv)[:, c] * gelu((A@Wg + bg)[:, c]),  Wv = W[:, 0:2048], Wg = W[:, 2048:4096]
#define GG_SMEM ((2 * A_BUF + 4 * B_BUF) * 4)

__global__ void __launch_bounds__(256) geglu_gemm_kernel(
    const float* __restrict__ A, const float* __restrict__ B,
    const float* __restrict__ bias, float* __restrict__ C)
{
    extern __shared__ float sm[];
    float* As = sm;
    float* Bs = sm + 2 * A_BUF;   // [2 stages][2 tiles][B_BUF]

    const int Kdim = 512, BN = 4096, CN = 2048;
    int tid  = threadIdx.x;
    int warp = tid >> 5, lane = tid & 31;
    int wm = warp & 1, wn = warp >> 1;
    int g  = lane >> 2, tg = lane & 3;
    int row0 = blockIdx.y * GBM;
    int col0 = blockIdx.x * GBN;     // within [0, 2048)

    float accV[4][4][4], accG[4][4][4];
#pragma unroll
    for (int i = 0; i < 4; i++)
#pragma unroll
        for (int j = 0; j < 4; j++)
#pragma unroll
            for (int r = 0; r < 4; r++) { accV[i][j][r] = 0.f; accG[i][j][r] = 0.f; }

    auto load_tiles = [&](int buf, int k0) {
#pragma unroll
        for (int i = 0; i < 4; i++) {
            int f = tid + 256 * i;
            int r = f >> 3, c4 = f & 7;
            cp_async16(&As[buf * A_BUF + r * ASTRIDE + c4 * 4],
                       A + (size_t)(row0 + r) * Kdim + k0 + c4 * 4);
        }
#pragma unroll
        for (int i = 0; i < 4; i++) {
            int f = tid + 256 * i;
            int r = f >> 5, c4 = f & 31;
            const float* src = B + (size_t)(k0 + r) * BN + col0 + c4 * 4;
            cp_async16(&Bs[buf * 2 * B_BUF + r * BSTRIDE + c4 * 4], src);
            cp_async16(&Bs[buf * 2 * B_BUF + B_BUF + r * BSTRIDE + c4 * 4], src + 2048);
        }
    };

    int nk = Kdim / GBK;
    load_tiles(0, 0);
    CP_COMMIT();

    int buf = 0;
    for (int t = 0; t < nk; t++) {
        CP_WAIT0();
        __syncthreads();
        if (t + 1 < nk) {
            load_tiles(buf ^ 1, (t + 1) * GBK);
            CP_COMMIT();
        }
        const float* Ab = &As[buf * A_BUF];
        const float* Bv = &Bs[buf * 2 * B_BUF];
        const float* Bg = Bv + B_BUF;
#pragma unroll
        for (int kk = 0; kk < 4; kk++) {
            int kb = kk * 8;
            unsigned af[4][4], bfv[4][2], bfg[4][2];
#pragma unroll
            for (int i = 0; i < 4; i++) {
                const float* ap = Ab + (wm * 64 + i * 16 + g) * ASTRIDE + kb + tg;
                af[i][0] = f2tf32(ap[0]);
                af[i][1] = f2tf32(ap[8 * ASTRIDE]);
                af[i][2] = f2tf32(ap[4]);
                af[i][3] = f2tf32(ap[8 * ASTRIDE + 4]);
            }
#pragma unroll
            for (int j = 0; j < 4; j++) {
                int off = (kb + tg) * BSTRIDE + wn * 32 + j * 8 + g;
                bfv[j][0] = f2tf32(Bv[off]);
                bfv[j][1] = f2tf32(Bv[off + 4 * BSTRIDE]);
                bfg[j][0] = f2tf32(Bg[off]);
                bfg[j][1] = f2tf32(Bg[off + 4 * BSTRIDE]);
            }
#pragma unroll
            for (int i = 0; i < 4; i++)
#pragma unroll
                for (int j = 0; j < 4; j++) {
                    mma_tf32(accV[i][j], af[i], bfv[j]);
                    mma_tf32(accG[i][j], af[i], bfg[j]);
                }
        }
        buf ^= 1;
    }

#pragma unroll
    for (int i = 0; i < 4; i++) {
        int r = row0 + wm * 64 + i * 16 + g;
#pragma unroll
        for (int j = 0; j < 4; j++) {
            int c = col0 + wn * 32 + j * 8 + tg * 2;
            float2 bv = *(const float2*)(bias + c);
            float2 bg = *(const float2*)(bias + c + 2048);
            float2 f0, f1;
            f0.x = (accV[i][j][0] + bv.x) * gelu_exact(accG[i][j][0] + bg.x);
            f0.y = (accV[i][j][1] + bv.y) * gelu_exact(accG[i][j][1] + bg.y);
            f1.x = (accV[i][j][2] + bv.x) * gelu_exact(accG[i][j][2] + bg.x);
            f1.y = (accV[i][j][3] + bv.y) * gelu_exact(accG[i][j][3] + bg.y);
            *(float2*)(C + (size_t)r * CN + c) = f0;
            *(float2*)(C + (size_t)(r + 8) * CN + c) = f1;
        }
    }
}

// ---------------- fused attention (vectorized) ----------------
#define KSTR 68
#define VSTR 260
#define ATTN_SMEM ((256*KSTR + 64*VSTR + 8*256 + 8*64) * 4)

__global__ void attn_kernel(const float* __restrict__ q, const float* __restrict__ k,
                            const float* __restrict__ v, float* __restrict__ o)
{
    extern __shared__ float sm[];
    float* Ks  = sm;                 // [256][KSTR]
    float* VsT = sm + 256*KSTR;      // [64][VSTR]  (transposed: [d][m])
    float* Ps  = VsT + 64*VSTR;      // [8][256]
    float* Qs  = Ps + 8*256;         // [8][64]
    int chunk = blockIdx.x & 7;
    int hh    = (blockIdx.x >> 3) & 7;
    int b     = blockIdx.x >> 6;
    int tid = threadIdx.x;
    int w = tid >> 5, l = tid & 31;

    for (int j = tid; j < 256*16; j += 256) {
        int m = j >> 4, f = j & 15;
        size_t gg = (size_t)(b*256 + m) * DD + hh*64 + f*4;
        float4 kv = *(const float4*)(k + gg);
        float4 vv = *(const float4*)(v + gg);
        float* kd = &Ks[m*KSTR + f*4];
        kd[0] = kv.x; kd[1] = kv.y; kd[2] = kv.z; kd[3] = kv.w;
        VsT[(f*4 + 0)*VSTR + m] = vv.x;
        VsT[(f*4 + 1)*VSTR + m] = vv.y;
        VsT[(f*4 + 2)*VSTR + m] = vv.z;
        VsT[(f*4 + 3)*VSTR + m] = vv.w;
    }
    __syncthreads();

    float* myP = Ps + w*256;
    float* myQ = Qs + w*64;
    for (int qi = w; qi < 128; qi += 8) {
        size_t qoff = ((size_t)b*1024 + chunk*128 + qi) * DD + hh*64;
        myQ[l]      = q[qoff + l]      * 0.125f;
        myQ[l + 32] = q[qoff + l + 32] * 0.125f;
        __syncwarp();
        float s[8];
#pragma unroll
        for (int t = 0; t < 8; t++) s[t] = 0.f;
#pragma unroll
        for (int d4 = 0; d4 < 16; d4++) {
            float4 q4 = ((const float4*)myQ)[d4];
#pragma unroll
            for (int t = 0; t < 8; t++) {
                float4 k4 = *(const float4*)&Ks[(l + 32*t)*KSTR + d4*4];
                s[t] += q4.x*k4.x + q4.y*k4.y + q4.z*k4.z + q4.w*k4.w;
            }
        }
        float mx = s[0];
#pragma unroll
        for (int t = 1; t < 8; t++) mx = fmaxf(mx, s[t]);
        for (int off = 16; off; off >>= 1) mx = fmaxf(mx, __shfl_xor_sync(0xffffffffu, mx, off));
        float sum = 0.f;
#pragma unroll
        for (int t = 0; t < 8; t++) { s[t] = __expf(s[t] - mx); sum += s[t]; }
        for (int off = 16; off; off >>= 1) sum += __shfl_xor_sync(0xffffffffu, sum, off);
        float inv = 1.0f / sum;
#pragma unroll
        for (int t = 0; t < 8; t++) myP[l + 32*t] = s[t] * inv;
        __syncwarp();
        float4 a0 = make_float4(0.f,0.f,0.f,0.f);
        float4 a1 = make_float4(0.f,0.f,0.f,0.f);
#pragma unroll 4
        for (int j4 = 0; j4 < 64; j4++) {
            float4 p  = ((const float4*)myP)[j4];
            float4 v0 = *(const float4*)&VsT[l*VSTR + j4*4];
            float4 v1 = *(const float4*)&VsT[(l + 32)*VSTR + j4*4];
            a0.x += p.x*v0.x; a0.y += p.y*v0.y; a0.z += p.z*v0.z; a0.w += p.w*v0.w;
            a1.x += p.x*v1.x; a1.y += p.y*v1.y; a1.z += p.z*v1.z; a1.w += p.w*v1.w;
        }
        o[qoff + l]      = (a0.x + a0.y) + (a0.z + a0.w);
        o[qoff + l + 32] = (a1.x + a1.y) + (a1.z + a1.w);
        __syncwarp();
    }
}

// ---------------- launch ----------------
extern "C" void kernel_launch(void* const* d_in, const int* in_sizes, int n_in,
                              void* d_out, int out_size)
{
    const float* x         = (const float*)d_in[0];
    const void*  ei        = d_in[1];
    const float* cond      = (const float*)d_in[2];
    const float* bn_w      = (const float*)d_in[3];
    const float* bn_b      = (const float*)d_in[4];
    const float* gcn_in_w  = (const float*)d_in[5];
    const float* gcn_in_b  = (const float*)d_in[6];
    const float* gcn_out_w = (const float*)d_in[7];
    const float* gcn_out_b = (const float*)d_in[8];
    const float* Wq        = (const float*)d_in[9];
    const float* Wk        = (const float*)d_in[10];
    const float* Wv        = (const float*)d_in[11];
    const float* Wo        = (const float*)d_in[12];
    const float* ln2_w     = (const float*)d_in[13];
    const float* ln2_b     = (const float*)d_in[14];
    const float* ln3_w     = (const float*)d_in[15];
    const float* ln3_b     = (const float*)d_in[16];
    const float* geglu_w   = (const float*)d_in[17];
    const float* geglu_b   = (const float*)d_in[18];
    const float* ffo_w     = (const float*)d_in[19];
    const float* ffo_b     = (const float*)d_in[20];
    float* out = (float*)d_out;
    long long E = (long long)in_sizes[1] / 2;

    float *p_h, *p_ln, *p_q, *p_xw, *p_ao, *p_k, *p_v, *p_f;
    cudaGetSymbolAddress((void**)&p_h,  g_h);
    cudaGetSymbolAddress((void**)&p_ln, g_ln);
    cudaGetSymbolAddress((void**)&p_q,  g_q);
    cudaGetSymbolAddress((void**)&p_xw, g_xw);
    cudaGetSymbolAddress((void**)&p_ao, g_ao);
    cudaGetSymbolAddress((void**)&p_k,  g_k);
    cudaGetSymbolAddress((void**)&p_v,  g_v);
    cudaGetSymbolAddress((void**)&p_f,  g_f);

    cudaFuncSetAttribute(attn_kernel, cudaFuncAttributeMaxDynamicSharedMemorySize, ATTN_SMEM);
    cudaFuncSetAttribute(mma_gemm_kernel<false,false>, cudaFuncAttributeMaxDynamicSharedMemorySize, GEMM_SMEM);
    cudaFuncSetAttribute(mma_gemm_kernel<true,false>,  cudaFuncAttributeMaxDynamicSharedMemorySize, GEMM_SMEM);
    cudaFuncSetAttribute(mma_gemm_kernel<true,true>,   cudaFuncAttributeMaxDynamicSharedMemorySize, GEMM_SMEM);
    cudaFuncSetAttribute(geglu_gemm_kernel, cudaFuncAttributeMaxDynamicSharedMemorySize, GG_SMEM);

    dim3 g512(4, 128);   // [16384,512]
    dim3 gkv(4, 32);     // [4096,512]
    dim3 gge(16, 128);   // [16384,2048] fused geglu

    // launches 1-5 (prologue), #6 = big GEMM (ncu -s 5 -c 1 captures it)
    init_kernel<<<64, 256>>>();
    detect_kernel<<<1, 256>>>((const unsigned int*)ei, (int)(E < 1024 ? E : 1024));
    bn_stats_kernel<<<128, 512>>>(x);
    bn_final_kernel<<<1, 512>>>(bn_w, bn_b);
    bn_apply_kernel<<<8192, 256>>>(x);                      // -> g_ln
    mma_gemm_kernel<false,false><<<g512, 256, GEMM_SMEM>>>(p_ln, gcn_in_w, nullptr, p_xw, DD, DD);

    // CSR build (once; reused by both GCNs)
    hist_kernel<<<512, 256>>>(ei, E);
    scan_kernel<<<1, 1024>>>();
    fill_kernel<<<512, 256>>>(ei, E);
    gcn_gather_kernel<false><<<NN, 128>>>(gcn_in_b, nullptr, p_h);

    for (int i = 0; i < LL; i++) {
        ln_kernel<<<NN, 128>>>(p_h, ln2_w + i*DD, ln2_b + i*DD, p_ln);
        mma_gemm_kernel<false,false><<<g512, 256, GEMM_SMEM>>>(p_ln, Wq + (size_t)i*DD*DD, nullptr, p_q, DD, DD);
        mma_gemm_kernel<false,false><<<gkv,  256, GEMM_SMEM>>>(cond, Wk + (size_t)i*DD*DD, nullptr, p_k, DD, DD);
        mma_gemm_kernel<false,false><<<gkv,  256, GEMM_SMEM>>>(cond, Wv + (size_t)i*DD*DD, nullptr, p_v, DD, DD);
        attn_kernel<<<1024, 256, ATTN_SMEM>>>(p_q, p_k, p_v, p_ao);
        mma_gemm_kernel<true,false><<<g512, 256, GEMM_SMEM>>>(p_ao, Wo + (size_t)i*DD*DD, nullptr, p_h, DD, DD);
        ln_kernel<<<NN, 128>>>(p_h, ln3_w + i*DD, ln3_b + i*DD, p_ln);
        geglu_gemm_kernel<<<gge, 256, GG_SMEM>>>(p_ln, geglu_w + (size_t)i*DD*4096,
                                                 geglu_b + (size_t)i*4096, p_f);
        mma_gemm_kernel<true,true><<<g512, 256, GEMM_SMEM>>>(p_f, ffo_w + (size_t)i*2048*DD,
                                                             ffo_b + (size_t)i*DD, p_h, DD, 2048);
    }

    mma_gemm_kernel<false,false><<<g512, 256, GEMM_SMEM>>>(p_h, gcn_out_w, nullptr, p_xw, DD, DD);
    gcn_gather_kernel<true><<<NN, 128>>>(gcn_out_b, x, out);
}

// round 4
// speedup vs baseline: 2.4493x; 1.0374x over previous
#include <cuda_runtime.h>
#include <math.h>

// Problem constants
#define NN   16384
#define DD   512
#define BSZ  16
#define MM   256
#define LL   4
#define EE   262144

// ---------------- scratch (device globals; no allocs allowed) ----------------
__device__ float g_h [NN*DD];
__device__ float g_ln[NN*DD];
__device__ float g_q [NN*DD];
__device__ float g_xw[NN*DD];
__device__ float g_ao[NN*DD];
__device__ float g_k [BSZ*MM*DD];
__device__ float g_v [BSZ*MM*DD];
__device__ float g_f [(size_t)NN*2048];
__device__ float g_wr[17301504];          // tf32-rounded weights
__device__ float g_condr[BSZ*MM*DD];      // tf32-rounded cond
__device__ float g_mu[DD];
__device__ float g_var[DD];
__device__ float g_scale[DD];
__device__ float g_shift[DD];
__device__ float g_dinv[NN];
__device__ int   g_count[NN];
__device__ int   g_cur[NN];
__device__ int   g_rowptr[NN+1];
__device__ int   g_srcs[EE];
__device__ int   g_is64;

// offsets into g_wr (floats)
#define OFF_GCNIN  0
#define OFF_GCNOUT 262144
#define OFF_WQ     524288
#define OFF_WK     1572864
#define OFF_WV     2621440
#define OFF_WO     3670016
#define OFF_GEGLU  4718592
#define OFF_FFO    13107200

// ---------------- helpers ----------------
__device__ __forceinline__ int edge_at(const void* ei, long long pos) {
    if (g_is64) return (int)((const long long*)ei)[pos];
    return ((const int*)ei)[pos];
}

__device__ __forceinline__ float gelu_exact(float x) {
    return 0.5f * x * (1.0f + erff(x * 0.70710678118654752f));
}

__device__ __forceinline__ unsigned f2tf32(float x) {
    unsigned y;
    asm("cvt.rna.tf32.f32 %0, %1;" : "=r"(y) : "f"(x));
    return y;
}
__device__ __forceinline__ float tf32r(float x) { return __uint_as_float(f2tf32(x)); }

__device__ __forceinline__ void cp_async16(void* smem, const void* gmem) {
    unsigned s = (unsigned)__cvta_generic_to_shared(smem);
    asm volatile("cp.async.cg.shared.global [%0], [%1], 16;\n" :: "r"(s), "l"(gmem));
}
#define CP_COMMIT() asm volatile("cp.async.commit_group;\n" ::)
#define CP_WAIT0()  asm volatile("cp.async.wait_group 0;\n" ::)

__device__ __forceinline__ void mma_tf32(float* d, const unsigned* a, const unsigned* b) {
    asm volatile(
      "mma.sync.aligned.m16n8k8.row.col.f32.tf32.tf32.f32 "
      "{%0,%1,%2,%3}, {%4,%5,%6,%7}, {%8,%9}, {%0,%1,%2,%3};\n"
      : "+f"(d[0]), "+f"(d[1]), "+f"(d[2]), "+f"(d[3])
      : "r"(a[0]), "r"(a[1]), "r"(a[2]), "r"(a[3]), "r"(b[0]), "r"(b[1]));
}

// ---------------- tf32 pre-round copy ----------------
__global__ void round_tf32_kernel(const float* __restrict__ src, float* __restrict__ dst, int n4) {
    int idx = blockIdx.x * blockDim.x + threadIdx.x;
    int stride = gridDim.x * blockDim.x;
    for (; idx < n4; idx += stride) {
        float4 v = ((const float4*)src)[idx];
        v.x = tf32r(v.x); v.y = tf32r(v.y); v.z = tf32r(v.z); v.w = tf32r(v.w);
        ((float4*)dst)[idx] = v;
    }
}

// ---------------- init ----------------
__global__ void init_kernel() {
    int i = blockIdx.x * blockDim.x + threadIdx.x;
    if (i < NN) g_count[i] = 0;
    if (i < DD) { g_mu[i] = 0.0f; g_var[i] = 0.0f; }
}

// ---------------- edge-index dtype sniffer ----------------
__global__ void detect_kernel(const unsigned int* __restrict__ raw, int n) {
    __shared__ int any;
    if (threadIdx.x == 0) any = 0;
    __syncthreads();
    int local = 0;
    for (int j = threadIdx.x; j < n; j += blockDim.x)
        if (raw[2*j + 1] != 0u) local = 1;
    if (local) atomicOr(&any, 1);
    __syncthreads();
    if (threadIdx.x == 0) g_is64 = any ? 0 : 1;
}

// ---------------- BatchNorm ----------------
__global__ void bn_stats_kernel(const float* __restrict__ x) {
    int c = threadIdx.x;
    size_t r0 = (size_t)blockIdx.x * 128;
    float s = 0.f, sq = 0.f;
    for (int r = 0; r < 128; r++) {
        float v = x[(r0 + r) * DD + c];
        s += v; sq += v * v;
    }
    atomicAdd(&g_mu[c], s);
    atomicAdd(&g_var[c], sq);
}

__global__ void bn_final_kernel(const float* __restrict__ w, const float* __restrict__ b) {
    int c = threadIdx.x;
    float mu  = g_mu[c]  * (1.0f / NN);
    float var = g_var[c] * (1.0f / NN) - mu * mu;
    float sc  = w[c] * rsqrtf(var + 1e-5f);
    g_scale[c] = sc;
    g_shift[c] = b[c] - mu * sc;
}

__global__ void bn_apply_kernel(const float* __restrict__ x) {
    size_t idx = (size_t)blockIdx.x * blockDim.x + threadIdx.x;
    int c4 = (int)(idx & 127);
    float4 xv = ((const float4*)x)[idx];
    float4 sc = ((const float4*)g_scale)[c4];
    float4 sh = ((const float4*)g_shift)[c4];
    float4 r;
    r.x = tf32r(xv.x * sc.x + sh.x); r.y = tf32r(xv.y * sc.y + sh.y);
    r.z = tf32r(xv.z * sc.z + sh.z); r.w = tf32r(xv.w * sc.w + sh.w);
    ((float4*)g_ln)[idx] = r;
}

// ---------------- CSR build ----------------
__global__ void hist_kernel(const void* __restrict__ ei, long long E) {
    long long stride = (long long)gridDim.x * blockDim.x;
    for (long long e = (long long)blockIdx.x * blockDim.x + threadIdx.x; e < E; e += stride) {
        int d = edge_at(ei, E + e);
        atomicAdd(&g_count[d], 1);
    }
}

__global__ void scan_kernel() {   // 1 block, 1024 threads; NN = 1024*16
    __shared__ int part[1024];
    int t = threadIdx.x;
    int base = t * 16;
    int loc[16];
    int s = 0;
#pragma unroll
    for (int j = 0; j < 16; j++) { loc[j] = g_count[base + j]; s += loc[j]; }
    part[t] = s;
    __syncthreads();
    for (int off = 1; off < 1024; off <<= 1) {
        int v = (t >= off) ? part[t - off] : 0;
        __syncthreads();
        part[t] += v;
        __syncthreads();
    }
    int run = part[t] - s;
#pragma unroll
    for (int j = 0; j < 16; j++) {
        g_rowptr[base + j] = run;
        run += loc[j];
        g_cur[base + j] = 0;
        g_dinv[base + j] = rsqrtf((float)loc[j] + 1.0f);
    }
    if (t == 1023) g_rowptr[NN] = part[1023];
}

__global__ void fill_kernel(const void* __restrict__ ei, long long E) {
    long long stride = (long long)gridDim.x * blockDim.x;
    for (long long e = (long long)blockIdx.x * blockDim.x + threadIdx.x; e < E; e += stride) {
        int s = edge_at(ei, e);
        int d = edge_at(ei, E + e);
        int pos = g_rowptr[d] + atomicAdd(&g_cur[d], 1);
        g_srcs[pos] = s;
    }
}

// ---------------- GCN gather ----------------
template<bool ADDX>
__global__ void gcn_gather_kernel(const float* __restrict__ bias,
                                  const float* __restrict__ xin,
                                  float* __restrict__ dst) {
    int n = blockIdx.x;
    int c = threadIdx.x;
    const float4* xw4 = (const float4*)g_xw;
    float di = g_dinv[n];
    float4 acc = ((const float4*)bias)[c];
    float4 sf = xw4[(size_t)n * 128 + c];
    float d2 = di * di;
    acc.x += d2 * sf.x; acc.y += d2 * sf.y; acc.z += d2 * sf.z; acc.w += d2 * sf.w;
    int e = g_rowptr[n], end = g_rowptr[n + 1];
    for (; e + 4 <= end; e += 4) {
        int s0 = g_srcs[e], s1 = g_srcs[e+1], s2 = g_srcs[e+2], s3 = g_srcs[e+3];
        float n0 = di * g_dinv[s0], n1 = di * g_dinv[s1];
        float n2 = di * g_dinv[s2], n3 = di * g_dinv[s3];
        float4 v0 = xw4[(size_t)s0 * 128 + c];
        float4 v1 = xw4[(size_t)s1 * 128 + c];
        float4 v2 = xw4[(size_t)s2 * 128 + c];
        float4 v3 = xw4[(size_t)s3 * 128 + c];
        acc.x += n0*v0.x + n1*v1.x + n2*v2.x + n3*v3.x;
        acc.y += n0*v0.y + n1*v1.y + n2*v2.y + n3*v3.y;
        acc.z += n0*v0.z + n1*v1.z + n2*v2.z + n3*v3.z;
        acc.w += n0*v0.w + n1*v1.w + n2*v2.w + n3*v3.w;
    }
    for (; e < end; e++) {
        int s0 = g_srcs[e];
        float n0 = di * g_dinv[s0];
        float4 v0 = xw4[(size_t)s0 * 128 + c];
        acc.x += n0*v0.x; acc.y += n0*v0.y; acc.z += n0*v0.z; acc.w += n0*v0.w;
    }
    if (ADDX) {
        float4 xv = ((const float4*)xin)[(size_t)n * 128 + c];
        acc.x += xv.x; acc.y += xv.y; acc.z += xv.z; acc.w += xv.w;
    }
    ((float4*)dst)[(size_t)n * 128 + c] = acc;
}

// ---------------- LayerNorm (tf32-rounded output) ----------------
__global__ void ln_kernel(const float* __restrict__ x, const float* __restrict__ w,
                          const float* __restrict__ b, float* __restrict__ y) {
    __shared__ float red[8];
    size_t row = blockIdx.x;
    int t = threadIdx.x;
    float4 v = ((const float4*)(x + row * DD))[t];
    float s  = v.x + v.y + v.z + v.w;
    float sq = v.x*v.x + v.y*v.y + v.z*v.z + v.w*v.w;
    for (int o = 16; o; o >>= 1) {
        s  += __shfl_xor_sync(0xffffffffu, s,  o);
        sq += __shfl_xor_sync(0xffffffffu, sq, o);
    }
    if ((t & 31) == 0) { red[t >> 5] = s; red[4 + (t >> 5)] = sq; }
    __syncthreads();
    s  = red[0] + red[1] + red[2] + red[3];
    sq = red[4] + red[5] + red[6] + red[7];
    float mean = s * (1.0f / DD);
    float var  = sq * (1.0f / DD) - mean * mean;
    float rstd = rsqrtf(var + 1e-5f);
    float4 wv = ((const float4*)w)[t];
    float4 bv = ((const float4*)b)[t];
    float4 o4;
    o4.x = tf32r((v.x - mean) * rstd * wv.x + bv.x);
    o4.y = tf32r((v.y - mean) * rstd * wv.y + bv.y);
    o4.z = tf32r((v.z - mean) * rstd * wv.z + bv.z);
    o4.w = tf32r((v.w - mean) * rstd * wv.w + bv.w);
    ((float4*)(y + row * DD))[t] = o4;
}

// ---------------- tf32 tensor-core GEMM (operands pre-rounded; no CVT) ----------------
#define GBM 128
#define GBN 128
#define GBK 32
#define ASTRIDE 36
#define BSTRIDE 136
#define A_BUF (GBM * ASTRIDE)
#define B_BUF (GBK * BSTRIDE)
#define GEMM_SMEM ((2 * A_BUF + 2 * B_BUF) * 4)

template<bool ACCUM, bool BIAS, bool CVTA>
__global__ void __launch_bounds__(256) mma_gemm_kernel(
    const float* __restrict__ A, const float* __restrict__ B,
    const float* __restrict__ bias, float* __restrict__ C,
    int Ndim, int Kdim)
{
    extern __shared__ float sm[];
    float* As = sm;
    float* Bs = sm + 2 * A_BUF;

    int tid  = threadIdx.x;
    int warp = tid >> 5, lane = tid & 31;
    int wm = warp & 1, wn = warp >> 1;
    int g  = lane >> 2, tg = lane & 3;
    int row0 = blockIdx.y * GBM;
    int col0 = blockIdx.x * GBN;

    float acc[4][4][4];
#pragma unroll
    for (int i = 0; i < 4; i++)
#pragma unroll
        for (int j = 0; j < 4; j++)
#pragma unroll
            for (int r = 0; r < 4; r++) acc[i][j][r] = 0.f;

    auto load_tiles = [&](int buf, int k0) {
#pragma unroll
        for (int i = 0; i < 4; i++) {
            int f = tid + 256 * i;
            int r = f >> 3, c4 = f & 7;
            cp_async16(&As[buf * A_BUF + r * ASTRIDE + c4 * 4],
                       A + (size_t)(row0 + r) * Kdim + k0 + c4 * 4);
        }
#pragma unroll
        for (int i = 0; i < 4; i++) {
            int f = tid + 256 * i;
            int r = f >> 5, c4 = f & 31;
            cp_async16(&Bs[buf * B_BUF + r * BSTRIDE + c4 * 4],
                       B + (size_t)(k0 + r) * Ndim + col0 + c4 * 4);
        }
    };

    int nk = Kdim / GBK;
    load_tiles(0, 0);
    CP_COMMIT();

    int buf = 0;
    for (int t = 0; t < nk; t++) {
        CP_WAIT0();
        __syncthreads();
        if (t + 1 < nk) {
            load_tiles(buf ^ 1, (t + 1) * GBK);
            CP_COMMIT();
        }
        const float* Ab = &As[buf * A_BUF];
        const float* Bb = &Bs[buf * B_BUF];
#pragma unroll
        for (int kk = 0; kk < 4; kk++) {
            int kb = kk * 8;
            unsigned af[4][4], bf[4][2];
#pragma unroll
            for (int i = 0; i < 4; i++) {
                const float* ap = Ab + (wm * 64 + i * 16 + g) * ASTRIDE + kb + tg;
                if (CVTA) {
                    af[i][0] = f2tf32(ap[0]);
                    af[i][1] = f2tf32(ap[8 * ASTRIDE]);
                    af[i][2] = f2tf32(ap[4]);
                    af[i][3] = f2tf32(ap[8 * ASTRIDE + 4]);
                } else {
                    af[i][0] = __float_as_uint(ap[0]);
                    af[i][1] = __float_as_uint(ap[8 * ASTRIDE]);
                    af[i][2] = __float_as_uint(ap[4]);
                    af[i][3] = __float_as_uint(ap[8 * ASTRIDE + 4]);
                }
            }
#pragma unroll
            for (int j = 0; j < 4; j++) {
                const float* bp = Bb + (kb + tg) * BSTRIDE + wn * 32 + j * 8 + g;
                bf[j][0] = __float_as_uint(bp[0]);
                bf[j][1] = __float_as_uint(bp[4 * BSTRIDE]);
            }
#pragma unroll
            for (int i = 0; i < 4; i++)
#pragma unroll
                for (int j = 0; j < 4; j++)
                    mma_tf32(acc[i][j], af[i], bf[j]);
        }
        buf ^= 1;
    }

#pragma unroll
    for (int i = 0; i < 4; i++) {
        int r = row0 + wm * 64 + i * 16 + g;
#pragma unroll
        for (int j = 0; j < 4; j++) {
            int c = col0 + wn * 32 + j * 8 + tg * 2;
            float2 v0 = make_float2(acc[i][j][0], acc[i][j][1]);
            float2 v1 = make_float2(acc[i][j][2], acc[i][j][3]);
            if (BIAS) {
                float2 bb = *(const float2*)(bias + c);
                v0.x += bb.x; v0.y += bb.y;
                v1.x += bb.x; v1.y += bb.y;
            }
            size_t o0 = (size_t)r * Ndim + c;
            size_t o1 = (size_t)(r + 8) * Ndim + c;
            if (ACCUM) {
                float2 e0 = *(const float2*)(C + o0);
                float2 e1 = *(const float2*)(C + o1);
                v0.x += e0.x; v0.y += e0.y;
                v1.x += e1.x; v1.y += e1.y;
            }
            *(float2*)(C + o0) = v0;
            *(float2*)(C + o1) = v1;
        }
    }
}

// ---------------- fused GEGLU GEMM (pre-rounded operands, rounded output) ----------------
#define GG_SMEM ((2 * A_BUF + 4 * B_BUF) * 4)

__global__ void __launch_bounds__(256) geglu_gemm_kernel(
    const float* __restrict__ A, const float* __restrict__ B,
    const float* __restrict__ bias, float* __restrict__ C)
{
    extern __shared__ float sm[];
    float* As = sm;
    float* Bs = sm + 2 * A_BUF;

    const int Kdim = 512, BN = 4096, CN = 2048;
    int tid  = threadIdx.x;
    int warp = tid >> 5, lane = tid & 31;
    int wm = warp & 1, wn = warp >> 1;
    int g  = lane >> 2, tg = lane & 3;
    int row0 = blockIdx.y * GBM;
    int col0 = blockIdx.x * GBN;

    float accV[4][4][4], accG[4][4][4];
#pragma unroll
    for (int i = 0; i < 4; i++)
#pragma unroll
        for (int j = 0; j < 4; j++)
#pragma unroll
            for (int r = 0; r < 4; r++) { accV[i][j][r] = 0.f; accG[i][j][r] = 0.f; }

    auto load_tiles = [&](int buf, int k0) {
#pragma unroll
        for (int i = 0; i < 4; i++) {
            int f = tid + 256 * i;
            int r = f >> 3, c4 = f & 7;
            cp_async16(&As[buf * A_BUF + r * ASTRIDE + c4 * 4],
                       A + (size_t)(row0 + r) * Kdim + k0 + c4 * 4);
        }
#pragma unroll
        for (int i = 0; i < 4; i++) {
            int f = tid + 256 * i;
            int r = f >> 5, c4 = f & 31;
            const float* src = B + (size_t)(k0 + r) * BN + col0 + c4 * 4;
            cp_async16(&Bs[buf * 2 * B_BUF + r * BSTRIDE + c4 * 4], src);
            cp_async16(&Bs[buf * 2 * B_BUF + B_BUF + r * BSTRIDE + c4 * 4], src + 2048);
        }
    };

    int nk = Kdim / GBK;
    load_tiles(0, 0);
    CP_COMMIT();

    int buf = 0;
    for (int t = 0; t < nk; t++) {
        CP_WAIT0();
        __syncthreads();
        if (t + 1 < nk) {
            load_tiles(buf ^ 1, (t + 1) * GBK);
            CP_COMMIT();
        }
        const float* Ab = &As[buf * A_BUF];
        const float* Bv = &Bs[buf * 2 * B_BUF];
        const float* Bg = Bv + B_BUF;
#pragma unroll
        for (int kk = 0; kk < 4; kk++) {
            int kb = kk * 8;
            unsigned af[4][4], bfv[4][2], bfg[4][2];
#pragma unroll
            for (int i = 0; i < 4; i++) {
                const float* ap = Ab + (wm * 64 + i * 16 + g) * ASTRIDE + kb + tg;
                af[i][0] = __float_as_uint(ap[0]);
                af[i][1] = __float_as_uint(ap[8 * ASTRIDE]);
                af[i][2] = __float_as_uint(ap[4]);
                af[i][3] = __float_as_uint(ap[8 * ASTRIDE + 4]);
            }
#pragma unroll
            for (int j = 0; j < 4; j++) {
                int off = (kb + tg) * BSTRIDE + wn * 32 + j * 8 + g;
                bfv[j][0] = __float_as_uint(Bv[off]);
                bfv[j][1] = __float_as_uint(Bv[off + 4 * BSTRIDE]);
                bfg[j][0] = __float_as_uint(Bg[off]);
                bfg[j][1] = __float_as_uint(Bg[off + 4 * BSTRIDE]);
            }
#pragma unroll
            for (int i = 0; i < 4; i++)
#pragma unroll
                for (int j = 0; j < 4; j++) {
                    mma_tf32(accV[i][j], af[i], bfv[j]);
                    mma_tf32(accG[i][j], af[i], bfg[j]);
                }
        }
        buf ^= 1;
    }

#pragma unroll
    for (int i = 0; i < 4; i++) {
        int r = row0 + wm * 64 + i * 16 + g;
#pragma unroll
        for (int j = 0; j < 4; j++) {
            int c = col0 + wn * 32 + j * 8 + tg * 2;
            float2 bv = *(const float2*)(bias + c);
            float2 bg = *(const float2*)(bias + c + 2048);
            float2 f0, f1;
            f0.x = tf32r((accV[i][j][0] + bv.x) * gelu_exact(accG[i][j][0] + bg.x));
            f0.y = tf32r((accV[i][j][1] + bv.y) * gelu_exact(accG[i][j][1] + bg.y));
            f1.x = tf32r((accV[i][j][2] + bv.x) * gelu_exact(accG[i][j][2] + bg.x));
            f1.y = tf32r((accV[i][j][3] + bv.y) * gelu_exact(accG[i][j][3] + bg.y));
            *(float2*)(C + (size_t)r * CN + c) = f0;
            *(float2*)(C + (size_t)(r + 8) * CN + c) = f1;
        }
    }
}

// ---------------- fused attention (tf32-rounded output) ----------------
#define KSTR 68
#define VSTR 260
#define ATTN_SMEM ((256*KSTR + 64*VSTR + 8*256 + 8*64) * 4)

__global__ void attn_kernel(const float* __restrict__ q, const float* __restrict__ k,
                            const float* __restrict__ v, float* __restrict__ o)
{
    extern __shared__ float sm[];
    float* Ks  = sm;
    float* VsT = sm + 256*KSTR;
    float* Ps  = VsT + 64*VSTR;
    float* Qs  = Ps + 8*256;
    int chunk = blockIdx.x & 7;
    int hh    = (blockIdx.x >> 3) & 7;
    int b     = blockIdx.x >> 6;
    int tid = threadIdx.x;
    int w = tid >> 5, l = tid & 31;

    for (int j = tid; j < 256*16; j += 256) {
        int m = j >> 4, f = j & 15;
        size_t gg = (size_t)(b*256 + m) * DD + hh*64 + f*4;
        float4 kv = *(const float4*)(k + gg);
        float4 vv = *(const float4*)(v + gg);
        float* kd = &Ks[m*KSTR + f*4];
        kd[0] = kv.x; kd[1] = kv.y; kd[2] = kv.z; kd[3] = kv.w;
        VsT[(f*4 + 0)*VSTR + m] = vv.x;
        VsT[(f*4 + 1)*VSTR + m] = vv.y;
        VsT[(f*4 + 2)*VSTR + m] = vv.z;
        VsT[(f*4 + 3)*VSTR + m] = vv.w;
    }
    __syncthreads();

    float* myP = Ps + w*256;
    float* myQ = Qs + w*64;
    for (int qi = w; qi < 128; qi += 8) {
        size_t qoff = ((size_t)b*1024 + chunk*128 + qi) * DD + hh*64;
        myQ[l]      = q[qoff + l]      * 0.125f;
        myQ[l + 32] = q[qoff + l + 32] * 0.125f;
        __syncwarp();
        float s[8];
#pragma unroll
        for (int t = 0; t < 8; t++) s[t] = 0.f;
#pragma unroll
        for (int d4 = 0; d4 < 16; d4++) {
            float4 q4 = ((const float4*)myQ)[d4];
#pragma unroll
            for (int t = 0; t < 8; t++) {
                float4 k4 = *(const float4*)&Ks[(l + 32*t)*KSTR + d4*4];
                s[t] += q4.x*k4.x + q4.y*k4.y + q4.z*k4.z + q4.w*k4.w;
            }
        }
        float mx = s[0];
#pragma unroll
        for (int t = 1; t < 8; t++) mx = fmaxf(mx, s[t]);
        for (int off = 16; off; off >>= 1) mx = fmaxf(mx, __shfl_xor_sync(0xffffffffu, mx, off));
        float sum = 0.f;
#pragma unroll
        for (int t = 0; t < 8; t++) { s[t] = __expf(s[t] - mx); sum += s[t]; }
        for (int off = 16; off; off >>= 1) sum += __shfl_xor_sync(0xffffffffu, sum, off);
        float inv = 1.0f / sum;
#pragma unroll
        for (int t = 0; t < 8; t++) myP[l + 32*t] = s[t] * inv;
        __syncwarp();
        float4 a0 = make_float4(0.f,0.f,0.f,0.f);
        float4 a1 = make_float4(0.f,0.f,0.f,0.f);
#pragma unroll 4
        for (int j4 = 0; j4 < 64; j4++) {
            float4 p  = ((const float4*)myP)[j4];
            float4 v0 = *(const float4*)&VsT[l*VSTR + j4*4];
            float4 v1 = *(const float4*)&VsT[(l + 32)*VSTR + j4*4];
            a0.x += p.x*v0.x; a0.y += p.y*v0.y; a0.z += p.z*v0.z; a0.w += p.w*v0.w;
            a1.x += p.x*v1.x; a1.y += p.y*v1.y; a1.z += p.z*v1.z; a1.w += p.w*v1.w;
        }
        o[qoff + l]      = tf32r((a0.x + a0.y) + (a0.z + a0.w));
        o[qoff + l + 32] = tf32r((a1.x + a1.y) + (a1.z + a1.w));
        __syncwarp();
    }
}

// ---------------- launch ----------------
extern "C" void kernel_launch(void* const* d_in, const int* in_sizes, int n_in,
                              void* d_out, int out_size)
{
    const float* x         = (const float*)d_in[0];
    const void*  ei        = d_in[1];
    const float* cond      = (const float*)d_in[2];
    const float* bn_w      = (const float*)d_in[3];
    const float* bn_b      = (const float*)d_in[4];
    const float* gcn_in_w  = (const float*)d_in[5];
    const float* gcn_in_b  = (const float*)d_in[6];
    const float* gcn_out_w = (const float*)d_in[7];
    const float* gcn_out_b = (const float*)d_in[8];
    const float* Wq        = (const float*)d_in[9];
    const float* Wk        = (const float*)d_in[10];
    const float* Wv        = (const float*)d_in[11];
    const float* Wo        = (const float*)d_in[12];
    const float* ln2_w     = (const float*)d_in[13];
    const float* ln2_b     = (const float*)d_in[14];
    const float* ln3_w     = (const float*)d_in[15];
    const float* ln3_b     = (const float*)d_in[16];
    const float* geglu_w   = (const float*)d_in[17];
    const float* geglu_b   = (const float*)d_in[18];
    const float* ffo_w     = (const float*)d_in[19];
    const float* ffo_b     = (const float*)d_in[20];
    float* out = (float*)d_out;
    long long E = (long long)in_sizes[1] / 2;

    float *p_h, *p_ln, *p_q, *p_xw, *p_ao, *p_k, *p_v, *p_f, *p_wr, *p_condr;
    cudaGetSymbolAddress((void**)&p_h,  g_h);
    cudaGetSymbolAddress((void**)&p_ln, g_ln);
    cudaGetSymbolAddress((void**)&p_q,  g_q);
    cudaGetSymbolAddress((void**)&p_xw, g_xw);
    cudaGetSymbolAddress((void**)&p_ao, g_ao);
    cudaGetSymbolAddress((void**)&p_k,  g_k);
    cudaGetSymbolAddress((void**)&p_v,  g_v);
    cudaGetSymbolAddress((void**)&p_f,  g_f);
    cudaGetSymbolAddress((void**)&p_wr, g_wr);
    cudaGetSymbolAddress((void**)&p_condr, g_condr);

    cudaFuncSetAttribute(attn_kernel, cudaFuncAttributeMaxDynamicSharedMemorySize, ATTN_SMEM);
    cudaFuncSetAttribute(mma_gemm_kernel<false,false,false>, cudaFuncAttributeMaxDynamicSharedMemorySize, GEMM_SMEM);
    cudaFuncSetAttribute(mma_gemm_kernel<true,false,false>,  cudaFuncAttributeMaxDynamicSharedMemorySize, GEMM_SMEM);
    cudaFuncSetAttribute(mma_gemm_kernel<true,true,false>,   cudaFuncAttributeMaxDynamicSharedMemorySize, GEMM_SMEM);
    cudaFuncSetAttribute(mma_gemm_kernel<false,false,true>,  cudaFuncAttributeMaxDynamicSharedMemorySize, GEMM_SMEM);
    cudaFuncSetAttribute(geglu_gemm_kernel, cudaFuncAttributeMaxDynamicSharedMemorySize, GG_SMEM);

    dim3 g512(4, 128);
    dim3 gkv(4, 32);
    dim3 gge(16, 128);

    // pre-round weights + cond into scratch
    round_tf32_kernel<<<512, 256>>>(gcn_in_w,  p_wr + OFF_GCNIN,  262144/4);
    round_tf32_kernel<<<512, 256>>>(gcn_out_w, p_wr + OFF_GCNOUT, 262144/4);
    round_tf32_kernel<<<512, 256>>>(Wq, p_wr + OFF_WQ, 1048576/4);
    round_tf32_kernel<<<512, 256>>>(Wk, p_wr + OFF_WK, 1048576/4);
    round_tf32_kernel<<<512, 256>>>(Wv, p_wr + OFF_WV, 1048576/4);
    round_tf32_kernel<<<512, 256>>>(Wo, p_wr + OFF_WO, 1048576/4);
    round_tf32_kernel<<<1024, 256>>>(geglu_w, p_wr + OFF_GEGLU, 8388608/4);
    round_tf32_kernel<<<1024, 256>>>(ffo_w,   p_wr + OFF_FFO,   4194304/4);
    round_tf32_kernel<<<512, 256>>>(cond, p_condr, (BSZ*MM*DD)/4);

    init_kernel<<<64, 256>>>();
    detect_kernel<<<1, 256>>>((const unsigned int*)ei, (int)(E < 1024 ? E : 1024));
    bn_stats_kernel<<<128, 512>>>(x);
    bn_final_kernel<<<1, 512>>>(bn_w, bn_b);
    bn_apply_kernel<<<8192, 256>>>(x);                      // -> g_ln (rounded)
    mma_gemm_kernel<false,false,false><<<g512, 256, GEMM_SMEM>>>(p_ln, p_wr + OFF_GCNIN, nullptr, p_xw, DD, DD);

    hist_kernel<<<512, 256>>>(ei, E);
    scan_kernel<<<1, 1024>>>();
    fill_kernel<<<512, 256>>>(ei, E);
    gcn_gather_kernel<false><<<NN, 128>>>(gcn_in_b, nullptr, p_h);

    for (int i = 0; i < LL; i++) {
        ln_kernel<<<NN, 128>>>(p_h, ln2_w + i*DD, ln2_b + i*DD, p_ln);
        mma_gemm_kernel<false,false,false><<<g512, 256, GEMM_SMEM>>>(p_ln, p_wr + OFF_WQ + (size_t)i*DD*DD, nullptr, p_q, DD, DD);
        mma_gemm_kernel<false,false,false><<<gkv,  256, GEMM_SMEM>>>(p_condr, p_wr + OFF_WK + (size_t)i*DD*DD, nullptr, p_k, DD, DD);
        mma_gemm_kernel<false,false,false><<<gkv,  256, GEMM_SMEM>>>(p_condr, p_wr + OFF_WV + (size_t)i*DD*DD, nullptr, p_v, DD, DD);
        attn_kernel<<<1024, 256, ATTN_SMEM>>>(p_q, p_k, p_v, p_ao);
        mma_gemm_kernel<true,false,false><<<g512, 256, GEMM_SMEM>>>(p_ao, p_wr + OFF_WO + (size_t)i*DD*DD, nullptr, p_h, DD, DD);
        ln_kernel<<<NN, 128>>>(p_h, ln3_w + i*DD, ln3_b + i*DD, p_ln);
        geglu_gemm_kernel<<<gge, 256, GG_SMEM>>>(p_ln, p_wr + OFF_GEGLU + (size_t)i*DD*4096,
                                                 geglu_b + (size_t)i*4096, p_f);
        mma_gemm_kernel<true,true,false><<<g512, 256, GEMM_SMEM>>>(p_f, p_wr + OFF_FFO + (size_t)i*2048*DD,
                                                                   ffo_b + (size_t)i*DD, p_h, DD, 2048);
    }

    mma_gemm_kernel<false,false,true><<<g512, 256, GEMM_SMEM>>>(p_h, p_wr + OFF_GCNOUT, nullptr, p_xw, DD, DD);
    gcn_gather_kernel<true><<<NN, 128>>>(gcn_out_b, x, out);
}

// round 5
// speedup vs baseline: 2.5383x; 1.0363x over previous
#include <cuda_runtime.h>
#include <math.h>

// Problem constants
#define NN   16384
#define DD   512
#define BSZ  16
#define MM   256
#define LL   4
#define EE   262144
#define KVSZ (BSZ*MM*DD)

// ---------------- scratch (device globals; no allocs allowed) ----------------
__device__ float g_h [NN*DD];
__device__ float g_ln[NN*DD];
__device__ float g_q [NN*DD];
__device__ float g_xw[NN*DD];
__device__ float g_ao[NN*DD];
__device__ float g_k [LL*KVSZ];
__device__ float g_v [LL*KVSZ];
__device__ float g_f [(size_t)NN*2048];
__device__ float g_wr[17301504];          // tf32-rounded weights
__device__ float g_condr[KVSZ];           // tf32-rounded cond
__device__ float g_mu[DD];
__device__ float g_var[DD];
__device__ float g_scale[DD];
__device__ float g_shift[DD];
__device__ float g_dinv[NN];
__device__ int   g_count[NN];
__device__ int   g_cur[NN];
__device__ int   g_rowptr[NN+1];
__device__ int   g_srcs[EE];
__device__ int   g_is64;

// offsets into g_wr (floats)
#define OFF_GCNIN  0
#define OFF_GCNOUT 262144
#define OFF_WQ     524288
#define OFF_WK     1572864
#define OFF_WV     2621440
#define OFF_WO     3670016
#define OFF_GEGLU  4718592
#define OFF_FFO    13107200

// ---------------- helpers ----------------
__device__ __forceinline__ int edge_at(const void* ei, long long pos) {
    if (g_is64) return (int)((const long long*)ei)[pos];
    return ((const int*)ei)[pos];
}

__device__ __forceinline__ float gelu_exact(float x) {
    return 0.5f * x * (1.0f + erff(x * 0.70710678118654752f));
}

__device__ __forceinline__ unsigned f2tf32(float x) {
    unsigned y;
    asm("cvt.rna.tf32.f32 %0, %1;" : "=r"(y) : "f"(x));
    return y;
}
__device__ __forceinline__ float tf32r(float x) { return __uint_as_float(f2tf32(x)); }

__device__ __forceinline__ void cp_async16(void* smem, const void* gmem) {
    unsigned s = (unsigned)__cvta_generic_to_shared(smem);
    asm volatile("cp.async.cg.shared.global [%0], [%1], 16;\n" :: "r"(s), "l"(gmem));
}
#define CP_COMMIT() asm volatile("cp.async.commit_group;\n" ::)
#define CP_WAIT0()  asm volatile("cp.async.wait_group 0;\n" ::)

__device__ __forceinline__ void mma_tf32(float* d, const unsigned* a, const unsigned* b) {
    asm volatile(
      "mma.sync.aligned.m16n8k8.row.col.f32.tf32.tf32.f32 "
      "{%0,%1,%2,%3}, {%4,%5,%6,%7}, {%8,%9}, {%0,%1,%2,%3};\n"
      : "+f"(d[0]), "+f"(d[1]), "+f"(d[2]), "+f"(d[3])
      : "r"(a[0]), "r"(a[1]), "r"(a[2]), "r"(a[3]), "r"(b[0]), "r"(b[1]));
}

// ---------------- tf32 pre-round copy ----------------
__global__ void round_tf32_kernel(const float* __restrict__ src, float* __restrict__ dst, int n4) {
    int idx = blockIdx.x * blockDim.x + threadIdx.x;
    int stride = gridDim.x * blockDim.x;
    for (; idx < n4; idx += stride) {
        float4 v = ((const float4*)src)[idx];
        v.x = tf32r(v.x); v.y = tf32r(v.y); v.z = tf32r(v.z); v.w = tf32r(v.w);
        ((float4*)dst)[idx] = v;
    }
}

// ---------------- init ----------------
__global__ void init_kernel() {
    int i = blockIdx.x * blockDim.x + threadIdx.x;
    if (i < NN) g_count[i] = 0;
    if (i < DD) { g_mu[i] = 0.0f; g_var[i] = 0.0f; }
}

// ---------------- edge-index dtype sniffer ----------------
__global__ void detect_kernel(const unsigned int* __restrict__ raw, int n) {
    __shared__ int any;
    if (threadIdx.x == 0) any = 0;
    __syncthreads();
    int local = 0;
    for (int j = threadIdx.x; j < n; j += blockDim.x)
        if (raw[2*j + 1] != 0u) local = 1;
    if (local) atomicOr(&any, 1);
    __syncthreads();
    if (threadIdx.x == 0) g_is64 = any ? 0 : 1;
}

// ---------------- BatchNorm ----------------
__global__ void bn_stats_kernel(const float* __restrict__ x) {
    int c = threadIdx.x;
    size_t r0 = (size_t)blockIdx.x * 128;
    float s = 0.f, sq = 0.f;
    for (int r = 0; r < 128; r++) {
        float v = x[(r0 + r) * DD + c];
        s += v; sq += v * v;
    }
    atomicAdd(&g_mu[c], s);
    atomicAdd(&g_var[c], sq);
}

__global__ void bn_final_kernel(const float* __restrict__ w, const float* __restrict__ b) {
    int c = threadIdx.x;
    float mu  = g_mu[c]  * (1.0f / NN);
    float var = g_var[c] * (1.0f / NN) - mu * mu;
    float sc  = w[c] * rsqrtf(var + 1e-5f);
    g_scale[c] = sc;
    g_shift[c] = b[c] - mu * sc;
}

__global__ void bn_apply_kernel(const float* __restrict__ x) {
    size_t idx = (size_t)blockIdx.x * blockDim.x + threadIdx.x;
    int c4 = (int)(idx & 127);
    float4 xv = ((const float4*)x)[idx];
    float4 sc = ((const float4*)g_scale)[c4];
    float4 sh = ((const float4*)g_shift)[c4];
    float4 r;
    r.x = tf32r(xv.x * sc.x + sh.x); r.y = tf32r(xv.y * sc.y + sh.y);
    r.z = tf32r(xv.z * sc.z + sh.z); r.w = tf32r(xv.w * sc.w + sh.w);
    ((float4*)g_ln)[idx] = r;
}

// ---------------- CSR build ----------------
__global__ void hist_kernel(const void* __restrict__ ei, long long E) {
    long long stride = (long long)gridDim.x * blockDim.x;
    for (long long e = (long long)blockIdx.x * blockDim.x + threadIdx.x; e < E; e += stride) {
        int d = edge_at(ei, E + e);
        atomicAdd(&g_count[d], 1);
    }
}

__global__ void scan_kernel() {
    __shared__ int part[1024];
    int t = threadIdx.x;
    int base = t * 16;
    int loc[16];
    int s = 0;
#pragma unroll
    for (int j = 0; j < 16; j++) { loc[j] = g_count[base + j]; s += loc[j]; }
    part[t] = s;
    __syncthreads();
    for (int off = 1; off < 1024; off <<= 1) {
        int v = (t >= off) ? part[t - off] : 0;
        __syncthreads();
        part[t] += v;
        __syncthreads();
    }
    int run = part[t] - s;
#pragma unroll
    for (int j = 0; j < 16; j++) {
        g_rowptr[base + j] = run;
        run += loc[j];
        g_cur[base + j] = 0;
        g_dinv[base + j] = rsqrtf((float)loc[j] + 1.0f);
    }
    if (t == 1023) g_rowptr[NN] = part[1023];
}

__global__ void fill_kernel(const void* __restrict__ ei, long long E) {
    long long stride = (long long)gridDim.x * blockDim.x;
    for (long long e = (long long)blockIdx.x * blockDim.x + threadIdx.x; e < E; e += stride) {
        int s = edge_at(ei, e);
        int d = edge_at(ei, E + e);
        int pos = g_rowptr[d] + atomicAdd(&g_cur[d], 1);
        g_srcs[pos] = s;
    }
}

// ---------------- GCN gather ----------------
template<bool ADDX>
__global__ void gcn_gather_kernel(const float* __restrict__ bias,
                                  const float* __restrict__ xin,
                                  float* __restrict__ dst) {
    int n = blockIdx.x;
    int c = threadIdx.x;
    const float4* xw4 = (const float4*)g_xw;
    float di = g_dinv[n];
    float4 acc = ((const float4*)bias)[c];
    float4 sf = xw4[(size_t)n * 128 + c];
    float d2 = di * di;
    acc.x += d2 * sf.x; acc.y += d2 * sf.y; acc.z += d2 * sf.z; acc.w += d2 * sf.w;
    int e = g_rowptr[n], end = g_rowptr[n + 1];
    for (; e + 4 <= end; e += 4) {
        int s0 = g_srcs[e], s1 = g_srcs[e+1], s2 = g_srcs[e+2], s3 = g_srcs[e+3];
        float n0 = di * g_dinv[s0], n1 = di * g_dinv[s1];
        float n2 = di * g_dinv[s2], n3 = di * g_dinv[s3];
        float4 v0 = xw4[(size_t)s0 * 128 + c];
        float4 v1 = xw4[(size_t)s1 * 128 + c];
        float4 v2 = xw4[(size_t)s2 * 128 + c];
        float4 v3 = xw4[(size_t)s3 * 128 + c];
        acc.x += n0*v0.x + n1*v1.x + n2*v2.x + n3*v3.x;
        acc.y += n0*v0.y + n1*v1.y + n2*v2.y + n3*v3.y;
        acc.z += n0*v0.z + n1*v1.z + n2*v2.z + n3*v3.z;
        acc.w += n0*v0.w + n1*v1.w + n2*v2.w + n3*v3.w;
    }
    for (; e < end; e++) {
        int s0 = g_srcs[e];
        float n0 = di * g_dinv[s0];
        float4 v0 = xw4[(size_t)s0 * 128 + c];
        acc.x += n0*v0.x; acc.y += n0*v0.y; acc.z += n0*v0.z; acc.w += n0*v0.w;
    }
    if (ADDX) {
        float4 xv = ((const float4*)xin)[(size_t)n * 128 + c];
        acc.x += xv.x; acc.y += xv.y; acc.z += xv.z; acc.w += xv.w;
    }
    ((float4*)dst)[(size_t)n * 128 + c] = acc;
}

// ---------------- LayerNorm (tf32-rounded output) ----------------
__global__ void ln_kernel(const float* __restrict__ x, const float* __restrict__ w,
                          const float* __restrict__ b, float* __restrict__ y) {
    __shared__ float red[8];
    size_t row = blockIdx.x;
    int t = threadIdx.x;
    float4 v = ((const float4*)(x + row * DD))[t];
    float s  = v.x + v.y + v.z + v.w;
    float sq = v.x*v.x + v.y*v.y + v.z*v.z + v.w*v.w;
    for (int o = 16; o; o >>= 1) {
        s  += __shfl_xor_sync(0xffffffffu, s,  o);
        sq += __shfl_xor_sync(0xffffffffu, sq, o);
    }
    if ((t & 31) == 0) { red[t >> 5] = s; red[4 + (t >> 5)] = sq; }
    __syncthreads();
    s  = red[0] + red[1] + red[2] + red[3];
    sq = red[4] + red[5] + red[6] + red[7];
    float mean = s * (1.0f / DD);
    float var  = sq * (1.0f / DD) - mean * mean;
    float rstd = rsqrtf(var + 1e-5f);
    float4 wv = ((const float4*)w)[t];
    float4 bv = ((const float4*)b)[t];
    float4 o4;
    o4.x = tf32r((v.x - mean) * rstd * wv.x + bv.x);
    o4.y = tf32r((v.y - mean) * rstd * wv.y + bv.y);
    o4.z = tf32r((v.z - mean) * rstd * wv.z + bv.z);
    o4.w = tf32r((v.w - mean) * rstd * wv.w + bv.w);
    ((float4*)(y + row * DD))[t] = o4;
}

// ---------------- tf32 tensor-core GEMM (2 CTAs/SM) ----------------
#define GBM 128
#define GBN 128
#define GBK 32
#define ASTRIDE 36
#define BSTRIDE 136
#define A_BUF (GBM * ASTRIDE)
#define B_BUF (GBK * BSTRIDE)
#define GEMM_SMEM ((2 * A_BUF + 2 * B_BUF) * 4)

template<bool ACCUM, bool BIAS, bool CVTA>
__global__ void __launch_bounds__(256, 2) mma_gemm_kernel(
    const float* __restrict__ A, const float* __restrict__ B,
    const float* __restrict__ bias, float* __restrict__ C,
    int Ndim, int Kdim)
{
    extern __shared__ float sm[];
    float* As = sm;
    float* Bs = sm + 2 * A_BUF;

    int tid  = threadIdx.x;
    int warp = tid >> 5, lane = tid & 31;
    int wm = warp & 1, wn = warp >> 1;
    int g  = lane >> 2, tg = lane & 3;
    int row0 = blockIdx.y * GBM;
    int col0 = blockIdx.x * GBN;

    float acc[4][4][4];
#pragma unroll
    for (int i = 0; i < 4; i++)
#pragma unroll
        for (int j = 0; j < 4; j++)
#pragma unroll
            for (int r = 0; r < 4; r++) acc[i][j][r] = 0.f;

    auto load_tiles = [&](int buf, int k0) {
#pragma unroll
        for (int i = 0; i < 4; i++) {
            int f = tid + 256 * i;
            int r = f >> 3, c4 = f & 7;
            cp_async16(&As[buf * A_BUF + r * ASTRIDE + c4 * 4],
                       A + (size_t)(row0 + r) * Kdim + k0 + c4 * 4);
        }
#pragma unroll
        for (int i = 0; i < 4; i++) {
            int f = tid + 256 * i;
            int r = f >> 5, c4 = f & 31;
            cp_async16(&Bs[buf * B_BUF + r * BSTRIDE + c4 * 4],
                       B + (size_t)(k0 + r) * Ndim + col0 + c4 * 4);
        }
    };

    int nk = Kdim / GBK;
    load_tiles(0, 0);
    CP_COMMIT();

    int buf = 0;
    for (int t = 0; t < nk; t++) {
        CP_WAIT0();
        __syncthreads();
        if (t + 1 < nk) {
            load_tiles(buf ^ 1, (t + 1) * GBK);
            CP_COMMIT();
        }
        const float* Ab = &As[buf * A_BUF];
        const float* Bb = &Bs[buf * B_BUF];
#pragma unroll
        for (int kk = 0; kk < 4; kk++) {
            int kb = kk * 8;
            unsigned af[4][4], bf[4][2];
#pragma unroll
            for (int i = 0; i < 4; i++) {
                const float* ap = Ab + (wm * 64 + i * 16 + g) * ASTRIDE + kb + tg;
                if (CVTA) {
                    af[i][0] = f2tf32(ap[0]);
                    af[i][1] = f2tf32(ap[8 * ASTRIDE]);
                    af[i][2] = f2tf32(ap[4]);
                    af[i][3] = f2tf32(ap[8 * ASTRIDE + 4]);
                } else {
                    af[i][0] = __float_as_uint(ap[0]);
                    af[i][1] = __float_as_uint(ap[8 * ASTRIDE]);
                    af[i][2] = __float_as_uint(ap[4]);
                    af[i][3] = __float_as_uint(ap[8 * ASTRIDE + 4]);
                }
            }
#pragma unroll
            for (int j = 0; j < 4; j++) {
                const float* bp = Bb + (kb + tg) * BSTRIDE + wn * 32 + j * 8 + g;
                bf[j][0] = __float_as_uint(bp[0]);
                bf[j][1] = __float_as_uint(bp[4 * BSTRIDE]);
            }
#pragma unroll
            for (int i = 0; i < 4; i++)
#pragma unroll
                for (int j = 0; j < 4; j++)
                    mma_tf32(acc[i][j], af[i], bf[j]);
        }
        buf ^= 1;
    }

#pragma unroll
    for (int i = 0; i < 4; i++) {
        int r = row0 + wm * 64 + i * 16 + g;
#pragma unroll
        for (int j = 0; j < 4; j++) {
            int c = col0 + wn * 32 + j * 8 + tg * 2;
            float2 v0 = make_float2(acc[i][j][0], acc[i][j][1]);
            float2 v1 = make_float2(acc[i][j][2], acc[i][j][3]);
            if (BIAS) {
                float2 bb = *(const float2*)(bias + c);
                v0.x += bb.x; v0.y += bb.y;
                v1.x += bb.x; v1.y += bb.y;
            }
            size_t o0 = (size_t)r * Ndim + c;
            size_t o1 = (size_t)(r + 8) * Ndim + c;
            if (ACCUM) {
                float2 e0 = *(const float2*)(C + o0);
                float2 e1 = *(const float2*)(C + o1);
                v0.x += e0.x; v0.y += e0.y;
                v1.x += e1.x; v1.y += e1.y;
            }
            *(float2*)(C + o0) = v0;
            *(float2*)(C + o1) = v1;
        }
    }
}

// ---------------- batched K/V projection GEMM ----------------
// grid (4, 32, 8): z = layer*2 + (0=K, 1=V). A = condr [4096,512].
__global__ void __launch_bounds__(256, 2) kv_gemm_kernel(
    const float* __restrict__ A, const float* __restrict__ WkBase,
    const float* __restrict__ WvBase, float* __restrict__ Kout, float* __restrict__ Vout)
{
    extern __shared__ float sm[];
    float* As = sm;
    float* Bs = sm + 2 * A_BUF;

    int z = blockIdx.z;
    int layer = z >> 1, isv = z & 1;
    const float* B = (isv ? WvBase : WkBase) + (size_t)layer * DD * DD;
    float* C = (isv ? Vout : Kout) + (size_t)layer * KVSZ;
    const int Ndim = DD, Kdim = DD;

    int tid  = threadIdx.x;
    int warp = tid >> 5, lane = tid & 31;
    int wm = warp & 1, wn = warp >> 1;
    int g  = lane >> 2, tg = lane & 3;
    int row0 = blockIdx.y * GBM;
    int col0 = blockIdx.x * GBN;

    float acc[4][4][4];
#pragma unroll
    for (int i = 0; i < 4; i++)
#pragma unroll
        for (int j = 0; j < 4; j++)
#pragma unroll
            for (int r = 0; r < 4; r++) acc[i][j][r] = 0.f;

    auto load_tiles = [&](int buf, int k0) {
#pragma unroll
        for (int i = 0; i < 4; i++) {
            int f = tid + 256 * i;
            int r = f >> 3, c4 = f & 7;
            cp_async16(&As[buf * A_BUF + r * ASTRIDE + c4 * 4],
                       A + (size_t)(row0 + r) * Kdim + k0 + c4 * 4);
        }
#pragma unroll
        for (int i = 0; i < 4; i++) {
            int f = tid + 256 * i;
            int r = f >> 5, c4 = f & 31;
            cp_async16(&Bs[buf * B_BUF + r * BSTRIDE + c4 * 4],
                       B + (size_t)(k0 + r) * Ndim + col0 + c4 * 4);
        }
    };

    int nk = Kdim / GBK;
    load_tiles(0, 0);
    CP_COMMIT();

    int buf = 0;
    for (int t = 0; t < nk; t++) {
        CP_WAIT0();
        __syncthreads();
        if (t + 1 < nk) {
            load_tiles(buf ^ 1, (t + 1) * GBK);
            CP_COMMIT();
        }
        const float* Ab = &As[buf * A_BUF];
        const float* Bb = &Bs[buf * B_BUF];
#pragma unroll
        for (int kk = 0; kk < 4; kk++) {
            int kb = kk * 8;
            unsigned af[4][4], bf[4][2];
#pragma unroll
            for (int i = 0; i < 4; i++) {
                const float* ap = Ab + (wm * 64 + i * 16 + g) * ASTRIDE + kb + tg;
                af[i][0] = __float_as_uint(ap[0]);
                af[i][1] = __float_as_uint(ap[8 * ASTRIDE]);
                af[i][2] = __float_as_uint(ap[4]);
                af[i][3] = __float_as_uint(ap[8 * ASTRIDE + 4]);
            }
#pragma unroll
            for (int j = 0; j < 4; j++) {
                const float* bp = Bb + (kb + tg) * BSTRIDE + wn * 32 + j * 8 + g;
                bf[j][0] = __float_as_uint(bp[0]);
                bf[j][1] = __float_as_uint(bp[4 * BSTRIDE]);
            }
#pragma unroll
            for (int i = 0; i < 4; i++)
#pragma unroll
                for (int j = 0; j < 4; j++)
                    mma_tf32(acc[i][j], af[i], bf[j]);
        }
        buf ^= 1;
    }

#pragma unroll
    for (int i = 0; i < 4; i++) {
        int r = row0 + wm * 64 + i * 16 + g;
#pragma unroll
        for (int j = 0; j < 4; j++) {
            int c = col0 + wn * 32 + j * 8 + tg * 2;
            *(float2*)(C + (size_t)r * Ndim + c) = make_float2(acc[i][j][0], acc[i][j][1]);
            *(float2*)(C + (size_t)(r + 8) * Ndim + c) = make_float2(acc[i][j][2], acc[i][j][3]);
        }
    }
}

// ---------------- fused GEGLU GEMM, 128x64 tiles (2 CTAs/SM) ----------------
#define GGN 64
#define GBSTRIDE 72
#define GB_BUF (GBK * GBSTRIDE)
#define GG_SMEM ((2 * A_BUF + 4 * GB_BUF) * 4)

__global__ void __launch_bounds__(256, 2) geglu_gemm_kernel(
    const float* __restrict__ A, const float* __restrict__ B,
    const float* __restrict__ bias, float* __restrict__ C)
{
    extern __shared__ float sm[];
    float* As = sm;
    float* Bs = sm + 2 * A_BUF;   // [2 stages][2 tiles][GB_BUF]

    const int Kdim = 512, BN = 4096, CN = 2048;
    int tid  = threadIdx.x;
    int warp = tid >> 5, lane = tid & 31;
    int wm = warp & 1, wn = warp >> 1;
    int g  = lane >> 2, tg = lane & 3;
    int row0 = blockIdx.y * GBM;
    int col0 = blockIdx.x * GGN;

    float accV[4][2][4], accG[4][2][4];
#pragma unroll
    for (int i = 0; i < 4; i++)
#pragma unroll
        for (int j = 0; j < 2; j++)
#pragma unroll
            for (int r = 0; r < 4; r++) { accV[i][j][r] = 0.f; accG[i][j][r] = 0.f; }

    auto load_tiles = [&](int buf, int k0) {
#pragma unroll
        for (int i = 0; i < 4; i++) {
            int f = tid + 256 * i;
            int r = f >> 3, c4 = f & 7;
            cp_async16(&As[buf * A_BUF + r * ASTRIDE + c4 * 4],
                       A + (size_t)(row0 + r) * Kdim + k0 + c4 * 4);
        }
        // B: 32 rows x 16 float4 per tile = 512 float4; 2 per thread per tile
#pragma unroll
        for (int i = 0; i < 2; i++) {
            int f = tid + 256 * i;
            int r = f >> 4, c4 = f & 15;
            const float* src = B + (size_t)(k0 + r) * BN + col0 + c4 * 4;
            cp_async16(&Bs[buf * 2 * GB_BUF + r * GBSTRIDE + c4 * 4], src);
            cp_async16(&Bs[buf * 2 * GB_BUF + GB_BUF + r * GBSTRIDE + c4 * 4], src + 2048);
        }
    };

    int nk = Kdim / GBK;
    load_tiles(0, 0);
    CP_COMMIT();

    int buf = 0;
    for (int t = 0; t < nk; t++) {
        CP_WAIT0();
        __syncthreads();
        if (t + 1 < nk) {
            load_tiles(buf ^ 1, (t + 1) * GBK);
            CP_COMMIT();
        }
        const float* Ab = &As[buf * A_BUF];
        const float* Bv = &Bs[buf * 2 * GB_BUF];
        const float* Bg = Bv + GB_BUF;
#pragma unroll
        for (int kk = 0; kk < 4; kk++) {
            int kb = kk * 8;
            unsigned af[4][4], bfv[2][2], bfg[2][2];
#pragma unroll
            for (int i = 0; i < 4; i++) {
                const float* ap = Ab + (wm * 64 + i * 16 + g) * ASTRIDE + kb + tg;
                af[i][0] = __float_as_uint(ap[0]);
                af[i][1] = __float_as_uint(ap[8 * ASTRIDE]);
                af[i][2] = __float_as_uint(ap[4]);
                af[i][3] = __float_as_uint(ap[8 * ASTRIDE + 4]);
            }
#pragma unroll
            for (int j = 0; j < 2; j++) {
                int off = (kb + tg) * GBSTRIDE + wn * 16 + j * 8 + g;
                bfv[j][0] = __float_as_uint(Bv[off]);
                bfv[j][1] = __float_as_uint(Bv[off + 4 * GBSTRIDE]);
                bfg[j][0] = __float_as_uint(Bg[off]);
                bfg[j][1] = __float_as_uint(Bg[off + 4 * GBSTRIDE]);
            }
#pragma unroll
            for (int i = 0; i < 4; i++)
#pragma unroll
                for (int j = 0; j < 2; j++) {
                    mma_tf32(accV[i][j], af[i], bfv[j]);
                    mma_tf32(accG[i][j], af[i], bfg[j]);
                }
        }
        buf ^= 1;
    }

#pragma unroll
    for (int i = 0; i < 4; i++) {
        int r = row0 + wm * 64 + i * 16 + g;
#pragma unroll
        for (int j = 0; j < 2; j++) {
            int c = col0 + wn * 16 + j * 8 + tg * 2;
            float2 bv = *(const float2*)(bias + c);
            float2 bg = *(const float2*)(bias + c + 2048);
            float2 f0, f1;
            f0.x = tf32r((accV[i][j][0] + bv.x) * gelu_exact(accG[i][j][0] + bg.x));
            f0.y = tf32r((accV[i][j][1] + bv.y) * gelu_exact(accG[i][j][1] + bg.y));
            f1.x = tf32r((accV[i][j][2] + bv.x) * gelu_exact(accG[i][j][2] + bg.x));
            f1.y = tf32r((accV[i][j][3] + bv.y) * gelu_exact(accG[i][j][3] + bg.y));
            *(float2*)(C + (size_t)r * CN + c) = f0;
            *(float2*)(C + (size_t)(r + 8) * CN + c) = f1;
        }
    }
}

// ---------------- fused attention (tf32-rounded output) ----------------
#define KSTR 68
#define VSTR 260
#define ATTN_SMEM ((256*KSTR + 64*VSTR + 8*256 + 8*64) * 4)

__global__ void attn_kernel(const float* __restrict__ q, const float* __restrict__ k,
                            const float* __restrict__ v, float* __restrict__ o)
{
    extern __shared__ float sm[];
    float* Ks  = sm;
    float* VsT = sm + 256*KSTR;
    float* Ps  = VsT + 64*VSTR;
    float* Qs  = Ps + 8*256;
    int chunk = blockIdx.x & 7;
    int hh    = (blockIdx.x >> 3) & 7;
    int b     = blockIdx.x >> 6;
    int tid = threadIdx.x;
    int w = tid >> 5, l = tid & 31;

    for (int j = tid; j < 256*16; j += 256) {
        int m = j >> 4, f = j & 15;
        size_t gg = (size_t)(b*256 + m) * DD + hh*64 + f*4;
        float4 kv = *(const float4*)(k + gg);
        float4 vv = *(const float4*)(v + gg);
        float* kd = &Ks[m*KSTR + f*4];
        kd[0] = kv.x; kd[1] = kv.y; kd[2] = kv.z; kd[3] = kv.w;
        VsT[(f*4 + 0)*VSTR + m] = vv.x;
        VsT[(f*4 + 1)*VSTR + m] = vv.y;
        VsT[(f*4 + 2)*VSTR + m] = vv.z;
        VsT[(f*4 + 3)*VSTR + m] = vv.w;
    }
    __syncthreads();

    float* myP = Ps + w*256;
    float* myQ = Qs + w*64;
    for (int qi = w; qi < 128; qi += 8) {
        size_t qoff = ((size_t)b*1024 + chunk*128 + qi) * DD + hh*64;
        myQ[l]      = q[qoff + l]      * 0.125f;
        myQ[l + 32] = q[qoff + l + 32] * 0.125f;
        __syncwarp();
        float s[8];
#pragma unroll
        for (int t = 0; t < 8; t++) s[t] = 0.f;
#pragma unroll
        for (int d4 = 0; d4 < 16; d4++) {
            float4 q4 = ((const float4*)myQ)[d4];
#pragma unroll
            for (int t = 0; t < 8; t++) {
                float4 k4 = *(const float4*)&Ks[(l + 32*t)*KSTR + d4*4];
                s[t] += q4.x*k4.x + q4.y*k4.y + q4.z*k4.z + q4.w*k4.w;
            }
        }
        float mx = s[0];
#pragma unroll
        for (int t = 1; t < 8; t++) mx = fmaxf(mx, s[t]);
        for (int off = 16; off; off >>= 1) mx = fmaxf(mx, __shfl_xor_sync(0xffffffffu, mx, off));
        float sum = 0.f;
#pragma unroll
        for (int t = 0; t < 8; t++) { s[t] = __expf(s[t] - mx); sum += s[t]; }
        for (int off = 16; off; off >>= 1) sum += __shfl_xor_sync(0xffffffffu, sum, off);
        float inv = 1.0f / sum;
#pragma unroll
        for (int t = 0; t < 8; t++) myP[l + 32*t] = s[t] * inv;
        __syncwarp();
        float4 a0 = make_float4(0.f,0.f,0.f,0.f);
        float4 a1 = make_float4(0.f,0.f,0.f,0.f);
#pragma unroll 4
        for (int j4 = 0; j4 < 64; j4++) {
            float4 p  = ((const float4*)myP)[j4];
            float4 v0 = *(const float4*)&VsT[l*VSTR + j4*4];
            float4 v1 = *(const float4*)&VsT[(l + 32)*VSTR + j4*4];
            a0.x += p.x*v0.x; a0.y += p.y*v0.y; a0.z += p.z*v0.z; a0.w += p.w*v0.w;
            a1.x += p.x*v1.x; a1.y += p.y*v1.y; a1.z += p.z*v1.z; a1.w += p.w*v1.w;
        }
        o[qoff + l]      = tf32r((a0.x + a0.y) + (a0.z + a0.w));
        o[qoff + l + 32] = tf32r((a1.x + a1.y) + (a1.z + a1.w));
        __syncwarp();
    }
}

// ---------------- launch ----------------
extern "C" void kernel_launch(void* const* d_in, const int* in_sizes, int n_in,
                              void* d_out, int out_size)
{
    const float* x         = (const float*)d_in[0];
    const void*  ei        = d_in[1];
    const float* cond      = (const float*)d_in[2];
    const float* bn_w      = (const float*)d_in[3];
    const float* bn_b      = (const float*)d_in[4];
    const float* gcn_in_w  = (const float*)d_in[5];
    const float* gcn_in_b  = (const float*)d_in[6];
    const float* gcn_out_w = (const float*)d_in[7];
    const float* gcn_out_b = (const float*)d_in[8];
    const float* Wq        = (const float*)d_in[9];
    const float* Wk        = (const float*)d_in[10];
    const float* Wv        = (const float*)d_in[11];
    const float* Wo        = (const float*)d_in[12];
    const float* ln2_w     = (const float*)d_in[13];
    const float* ln2_b     = (const float*)d_in[14];
    const float* ln3_w     = (const float*)d_in[15];
    const float* ln3_b     = (const float*)d_in[16];
    const float* geglu_w   = (const float*)d_in[17];
    const float* geglu_b   = (const float*)d_in[18];
    const float* ffo_w     = (const float*)d_in[19];
    const float* ffo_b     = (const float*)d_in[20];
    float* out = (float*)d_out;
    long long E = (long long)in_sizes[1] / 2;

    float *p_h, *p_ln, *p_q, *p_xw, *p_ao, *p_k, *p_v, *p_f, *p_wr, *p_condr;
    cudaGetSymbolAddress((void**)&p_h,  g_h);
    cudaGetSymbolAddress((void**)&p_ln, g_ln);
    cudaGetSymbolAddress((void**)&p_q,  g_q);
    cudaGetSymbolAddress((void**)&p_xw, g_xw);
    cudaGetSymbolAddress((void**)&p_ao, g_ao);
    cudaGetSymbolAddress((void**)&p_k,  g_k);
    cudaGetSymbolAddress((void**)&p_v,  g_v);
    cudaGetSymbolAddress((void**)&p_f,  g_f);
    cudaGetSymbolAddress((void**)&p_wr, g_wr);
    cudaGetSymbolAddress((void**)&p_condr, g_condr);

    cudaFuncSetAttribute(attn_kernel, cudaFuncAttributeMaxDynamicSharedMemorySize, ATTN_SMEM);
    cudaFuncSetAttribute(mma_gemm_kernel<false,false,false>, cudaFuncAttributeMaxDynamicSharedMemorySize, GEMM_SMEM);
    cudaFuncSetAttribute(mma_gemm_kernel<true,false,false>,  cudaFuncAttributeMaxDynamicSharedMemorySize, GEMM_SMEM);
    cudaFuncSetAttribute(mma_gemm_kernel<true,true,false>,   cudaFuncAttributeMaxDynamicSharedMemorySize, GEMM_SMEM);
    cudaFuncSetAttribute(mma_gemm_kernel<false,false,true>,  cudaFuncAttributeMaxDynamicSharedMemorySize, GEMM_SMEM);
    cudaFuncSetAttribute(kv_gemm_kernel, cudaFuncAttributeMaxDynamicSharedMemorySize, GEMM_SMEM);
    cudaFuncSetAttribute(geglu_gemm_kernel, cudaFuncAttributeMaxDynamicSharedMemorySize, GG_SMEM);

    dim3 g512(4, 128);
    dim3 gkv(4, 32, 8);     // batched K/V: 4 layers x {K,V}
    dim3 gge(32, 128);      // 128x64 tiles over [16384, 2048]

    // pre-round weights + cond into scratch
    round_tf32_kernel<<<512, 256>>>(gcn_in_w,  p_wr + OFF_GCNIN,  262144/4);
    round_tf32_kernel<<<512, 256>>>(gcn_out_w, p_wr + OFF_GCNOUT, 262144/4);
    round_tf32_kernel<<<512, 256>>>(Wq, p_wr + OFF_WQ, 1048576/4);
    round_tf32_kernel<<<512, 256>>>(Wk, p_wr + OFF_WK, 1048576/4);
    round_tf32_kernel<<<512, 256>>>(Wv, p_wr + OFF_WV, 1048576/4);
    round_tf32_kernel<<<512, 256>>>(Wo, p_wr + OFF_WO, 1048576/4);
    round_tf32_kernel<<<1024, 256>>>(geglu_w, p_wr + OFF_GEGLU, 8388608/4);
    round_tf32_kernel<<<1024, 256>>>(ffo_w,   p_wr + OFF_FFO,   4194304/4);
    round_tf32_kernel<<<512, 256>>>(cond, p_condr, KVSZ/4);

    init_kernel<<<64, 256>>>();
    detect_kernel<<<1, 256>>>((const unsigned int*)ei, (int)(E < 1024 ? E : 1024));
    bn_stats_kernel<<<128, 512>>>(x);
    bn_final_kernel<<<1, 512>>>(bn_w, bn_b);
    bn_apply_kernel<<<8192, 256>>>(x);                      // -> g_ln (rounded)

    // all K/V projections for all layers, one launch
    kv_gemm_kernel<<<gkv, 256, GEMM_SMEM>>>(p_condr, p_wr + OFF_WK, p_wr + OFF_WV, p_k, p_v);

    mma_gemm_kernel<false,false,false><<<g512, 256, GEMM_SMEM>>>(p_ln, p_wr + OFF_GCNIN, nullptr, p_xw, DD, DD);

    hist_kernel<<<512, 256>>>(ei, E);
    scan_kernel<<<1, 1024>>>();
    fill_kernel<<<512, 256>>>(ei, E);
    gcn_gather_kernel<false><<<NN, 128>>>(gcn_in_b, nullptr, p_h);

    for (int i = 0; i < LL; i++) {
        ln_kernel<<<NN, 128>>>(p_h, ln2_w + i*DD, ln2_b + i*DD, p_ln);
        mma_gemm_kernel<false,false,false><<<g512, 256, GEMM_SMEM>>>(p_ln, p_wr + OFF_WQ + (size_t)i*DD*DD, nullptr, p_q, DD, DD);
        attn_kernel<<<1024, 256, ATTN_SMEM>>>(p_q, p_k + (size_t)i*KVSZ, p_v + (size_t)i*KVSZ, p_ao);
        mma_gemm_kernel<true,false,false><<<g512, 256, GEMM_SMEM>>>(p_ao, p_wr + OFF_WO + (size_t)i*DD*DD, nullptr, p_h, DD, DD);
        ln_kernel<<<NN, 128>>>(p_h, ln3_w + i*DD, ln3_b + i*DD, p_ln);
        geglu_gemm_kernel<<<gge, 256, GG_SMEM>>>(p_ln, p_wr + OFF_GEGLU + (size_t)i*DD*4096,
                                                 geglu_b + (size_t)i*4096, p_f);
        mma_gemm_kernel<true,true,false><<<g512, 256, GEMM_SMEM>>>(p_f, p_wr + OFF_FFO + (size_t)i*2048*DD,
                                                                   ffo_b + (size_t)i*DD, p_h, DD, 2048);
    }

    mma_gemm_kernel<false,false,true><<<g512, 256, GEMM_SMEM>>>(p_h, p_wr + OFF_GCNOUT, nullptr, p_xw, DD, DD);
    gcn_gather_kernel<true><<<NN, 128>>>(gcn_out_b, x, out);
}